// round 5
// baseline (speedup 1.0000x reference)
#include <cuda_runtime.h>

// ---------------- constants ----------------
#define BB 64
#define C_IN 256
#define CH 128
#define NPH 64
#define RR 16
#define SP 256          // R*R spatial
#define ED 128
#define CBQ 8
#define NL 4
#define NE 1024
#define C_OUT 256
#define FLAT_PH 16384   // NPH*R*R
#define FLAT_Z 4096     // ED*CB*NL
#define NROWS 2048      // B*CB*NL
#define OUT_ELEMS (BB*C_OUT*SP)   // 4194304

typedef unsigned long long u64;

#define DINLINE __device__ __forceinline__

DINLINE u64 pack2(float lo, float hi){ u64 r; asm("mov.b64 %0, {%1,%2};" : "=l"(r) : "f"(lo), "f"(hi)); return r; }
DINLINE void unpack2(u64 v, float &lo, float &hi){ asm("mov.b64 {%0,%1}, %2;" : "=f"(lo), "=f"(hi) : "l"(v)); }
DINLINE u64 fma2(u64 a, u64 b, u64 c){ u64 d; asm("fma.rn.f32x2 %0, %1, %2, %3;" : "=l"(d) : "l"(a), "l"(b), "l"(c)); return d; }
DINLINE float silu_f(float x){ return x / (1.f + __expf(-x)); }

// 4x4 microtile update using packed f32x2 FMAs (8 FFMA2 per k-step)
DINLINE void fma_4x4(u64 (&acc)[4][2], float4 a, float4 b){
    u64 b01 = pack2(b.x, b.y), b23 = pack2(b.z, b.w);
    u64 aa;
    aa = pack2(a.x, a.x); acc[0][0]=fma2(aa,b01,acc[0][0]); acc[0][1]=fma2(aa,b23,acc[0][1]);
    aa = pack2(a.y, a.y); acc[1][0]=fma2(aa,b01,acc[1][0]); acc[1][1]=fma2(aa,b23,acc[1][1]);
    aa = pack2(a.z, a.z); acc[2][0]=fma2(aa,b01,acc[2][0]); acc[2][1]=fma2(aa,b23,acc[2][1]);
    aa = pack2(a.w, a.w); acc[3][0]=fma2(aa,b01,acc[3][0]); acc[3][1]=fma2(aa,b23,acc[3][1]);
}

// ---------------- scratch (device globals; no allocs) ----------------
__device__ float g_hphylo[BB*FLAT_PH];   // conv_in phylo half (pre-LN)
__device__ float g_himg  [BB*FLAT_PH];   // conv_in img half (raw)
__device__ float g_hn    [BB*FLAT_PH];   // layernormed phylo
__device__ float g_stats [BB*2];         // mu, rstd per batch
__device__ float g_zp    [8*BB*FLAT_Z];  // split-K partials (8MB, shared by both MLPs)
__device__ float g_z     [BB*FLAT_Z];    // z
__device__ float g_zq    [BB*FLAT_Z];    // quantized z (codebook gather)
__device__ float g_hout  [BB*FLAT_PH];   // mlp_out output
__device__ float g_cnorm [NE];           // |codebook_e|^2
__device__ u64   g_key   [NROWS];        // packed (sortable_dist<<32)|idx
__device__ float g_losspart[NROWS];

// ---------------- conv_in: h = W @ silu(x) + b, split into phylo/img ----------------
__global__ void __launch_bounds__(256) conv_in_k(const float* __restrict__ x,
                                                 const float* __restrict__ W,
                                                 const float* __restrict__ bias)
{
    // grid: 64 b * 2 o-tiles * 4 p-tiles = 512 blocks
    int bidx = blockIdx.x;
    int b  = bidx >> 3;
    int ot = (bidx >> 2) & 1;
    int pt = bidx & 3;
    int obase = ot * 64, pbase = pt * 64;

    __shared__ float Ws[2][16][68];  // Ws[buf][c][o]
    __shared__ float Xs[2][16][68];  // Xs[buf][c][p] (silu applied)

    int tid = threadIdx.x;
    int tx = tid & 15, ty = tid >> 4;
    int m0 = ty * 4, j0 = tx * 4;          // m0 -> o, j0 -> p
    int lr = tid >> 2, kq = (tid & 3) * 4; // weight load mapping
    int cl = tid >> 4, pl = (tid & 15) * 4;// x load mapping

    const float* Wp = W + (obase+lr)*C_IN + kq;
    const float* Xp = x + b*(C_IN*SP) + cl*SP + pbase + pl;

    u64 acc[4][2];
    #pragma unroll
    for (int i=0;i<4;i++){ acc[i][0]=pack2(0.f,0.f); acc[i][1]=acc[i][0]; }

    const int nt = C_IN/16;
    float4 wv = *(const float4*)(Wp);
    float4 xv = *(const float4*)(Xp);
    Ws[0][kq+0][lr]=wv.x; Ws[0][kq+1][lr]=wv.y; Ws[0][kq+2][lr]=wv.z; Ws[0][kq+3][lr]=wv.w;
    Xs[0][cl][pl+0]=silu_f(xv.x); Xs[0][cl][pl+1]=silu_f(xv.y);
    Xs[0][cl][pl+2]=silu_f(xv.z); Xs[0][cl][pl+3]=silu_f(xv.w);
    __syncthreads();

    for (int t = 0; t < nt; t++){
        int cur = t & 1;
        bool more = (t+1) < nt;
        if (more){
            wv = *(const float4*)(Wp + (t+1)*16);
            xv = *(const float4*)(Xp + (t+1)*16*SP);
        }
        #pragma unroll
        for (int k=0;k<16;k++){
            float4 a = *(const float4*)&Ws[cur][k][m0];
            float4 bv = *(const float4*)&Xs[cur][k][j0];
            fma_4x4(acc, a, bv);
        }
        if (more){
            int nx = cur^1;
            Ws[nx][kq+0][lr]=wv.x; Ws[nx][kq+1][lr]=wv.y; Ws[nx][kq+2][lr]=wv.z; Ws[nx][kq+3][lr]=wv.w;
            Xs[nx][cl][pl+0]=silu_f(xv.x); Xs[nx][cl][pl+1]=silu_f(xv.y);
            Xs[nx][cl][pl+2]=silu_f(xv.z); Xs[nx][cl][pl+3]=silu_f(xv.w);
        }
        __syncthreads();
    }

    #pragma unroll
    for (int i=0;i<4;i++){
        int o = obase + m0 + i;
        float bo = bias[o];
        float v0,v1,v2,v3;
        unpack2(acc[i][0], v0, v1); unpack2(acc[i][1], v2, v3);
        float4 ov; ov.x=v0+bo; ov.y=v1+bo; ov.z=v2+bo; ov.w=v3+bo;
        float* dst = (o < NPH) ? (g_hphylo + b*FLAT_PH + o*SP)
                               : (g_himg   + b*FLAT_PH + (o-NPH)*SP);
        *(float4*)(dst + pbase + j0) = ov;
    }
}

// ---------------- layernorm stats (per batch over 16384 elems) ----------------
__global__ void __launch_bounds__(256) ln_stats_k()
{
    int b = blockIdx.x;
    const float4* p = (const float4*)(g_hphylo + b*FLAT_PH);
    float s = 0.f, s2 = 0.f;
    for (int i = threadIdx.x; i < FLAT_PH/4; i += 256){
        float4 v = p[i];
        s  += v.x + v.y + v.z + v.w;
        s2 += v.x*v.x + v.y*v.y + v.z*v.z + v.w*v.w;
    }
    __shared__ float rs[256], rq[256];
    rs[threadIdx.x] = s; rq[threadIdx.x] = s2;
    __syncthreads();
    for (int off = 128; off; off >>= 1){
        if (threadIdx.x < off){ rs[threadIdx.x]+=rs[threadIdx.x+off]; rq[threadIdx.x]+=rq[threadIdx.x+off]; }
        __syncthreads();
    }
    if (threadIdx.x == 0){
        float mu = rs[0] * (1.f/FLAT_PH);
        float var = rq[0] * (1.f/FLAT_PH) - mu*mu;
        g_stats[b*2+0] = mu;
        g_stats[b*2+1] = rsqrtf(var + 1e-5f);
    }
}

__global__ void __launch_bounds__(256) ln_norm_k(const float* __restrict__ lnw,
                                                 const float* __restrict__ lnb)
{
    int b = blockIdx.x;
    int base = blockIdx.y * 1024 + threadIdx.x * 4;
    float mu = g_stats[b*2+0], rstd = g_stats[b*2+1];
    float4 v = *(const float4*)(g_hphylo + b*FLAT_PH + base);
    float4 w = *(const float4*)(lnw + base);
    float4 bb = *(const float4*)(lnb + base);
    float4 o;
    o.x = (v.x-mu)*rstd*w.x + bb.x;
    o.y = (v.y-mu)*rstd*w.y + bb.y;
    o.z = (v.z-mu)*rstd*w.z + bb.z;
    o.w = (v.w-mu)*rstd*w.w + bb.w;
    *(float4*)(g_hn + b*FLAT_PH + base) = o;
}

// ---------------- generic skinny GEMM: C[64 x N] = A[64 x K] @ W[N x K]^T ----------------
// grid.x = N/64 tiles, grid.y = K splits (kchunk each). Partial split s writes C + s*64*N.
// Register double-buffered: prefetch next k-tile during compute.
__global__ void __launch_bounds__(256) mlp_gemm_k(const float* __restrict__ A,
                                                  const float* __restrict__ W,
                                                  float* __restrict__ C,
                                                  int K, int N, int kchunk)
{
    __shared__ float As[2][16][68];   // As[buf][k][m]
    __shared__ float Bs[2][16][68];   // Bs[buf][k][j]
    int tid = threadIdx.x;
    int jbase = blockIdx.x * 64;
    int k0 = blockIdx.y * kchunk;
    float* Cout = C + (size_t)blockIdx.y * 64 * N;
    int tx = tid & 15, ty = tid >> 4;
    int m0 = ty * 4, j0 = tx * 4;
    int lr = tid >> 2, kq = (tid & 3) * 4;

    u64 acc[4][2];
    #pragma unroll
    for (int i=0;i<4;i++){ acc[i][0]=pack2(0.f,0.f); acc[i][1]=acc[i][0]; }

    const float* Ap = A + (size_t)lr * K + k0 + kq;
    const float* Wp = W + (size_t)(jbase + lr) * K + k0 + kq;

    const int nt = kchunk >> 4;
    float4 av = *(const float4*)(Ap);
    float4 wv = *(const float4*)(Wp);
    As[0][kq+0][lr]=av.x; As[0][kq+1][lr]=av.y; As[0][kq+2][lr]=av.z; As[0][kq+3][lr]=av.w;
    Bs[0][kq+0][lr]=wv.x; Bs[0][kq+1][lr]=wv.y; Bs[0][kq+2][lr]=wv.z; Bs[0][kq+3][lr]=wv.w;
    __syncthreads();

    for (int t = 0; t < nt; t++){
        int cur = t & 1;
        bool more = (t+1) < nt;
        if (more){
            av = *(const float4*)(Ap + (t+1)*16);
            wv = *(const float4*)(Wp + (t+1)*16);
        }
        #pragma unroll
        for (int k=0;k<16;k++){
            float4 a = *(const float4*)&As[cur][k][m0];
            float4 b = *(const float4*)&Bs[cur][k][j0];
            fma_4x4(acc, a, b);
        }
        if (more){
            int nx = cur^1;
            As[nx][kq+0][lr]=av.x; As[nx][kq+1][lr]=av.y; As[nx][kq+2][lr]=av.z; As[nx][kq+3][lr]=av.w;
            Bs[nx][kq+0][lr]=wv.x; Bs[nx][kq+1][lr]=wv.y; Bs[nx][kq+2][lr]=wv.z; Bs[nx][kq+3][lr]=wv.w;
        }
        __syncthreads();
    }

    #pragma unroll
    for (int i=0;i<4;i++){
        float v0,v1,v2,v3;
        unpack2(acc[i][0], v0, v1); unpack2(acc[i][1], v2, v3);
        float4 o; o.x=v0; o.y=v1; o.z=v2; o.w=v3;
        *(float4*)(Cout + (size_t)(m0+i)*N + jbase + j0) = o;
    }
}

// ---------------- combine nsplit partials + bias ----------------
__global__ void __launch_bounds__(256) combine_k(const float* __restrict__ P,
                                                 float* __restrict__ out,
                                                 const float* __restrict__ bias,
                                                 int nsplit, int total, int N)
{
    int i = blockIdx.x * 256 + threadIdx.x;      // float4 index
    const float4* P4 = (const float4*)P;
    float4 s = P4[i];
    int stride = total >> 2;
    for (int sp = 1; sp < nsplit; sp++){
        float4 a = P4[i + sp*stride];
        s.x+=a.x; s.y+=a.y; s.z+=a.z; s.w+=a.w;
    }
    int j = (i * 4) & (N - 1);
    float4 bv = *(const float4*)(bias + j);
    s.x+=bv.x; s.y+=bv.y; s.z+=bv.z; s.w+=bv.w;
    ((float4*)out)[i] = s;
}

// ---------------- codebook norms ----------------
__global__ void __launch_bounds__(256) cnorm_k(const float* __restrict__ cb)
{
    int e = blockIdx.x * 256 + threadIdx.x;
    const float4* r = (const float4*)(cb + e*ED);
    float s = 0.f;
    #pragma unroll 8
    for (int i = 0; i < ED/4; i++){
        float4 v = r[i];
        s += v.x*v.x + v.y*v.y + v.z*v.z + v.w*v.w;
    }
    g_cnorm[e] = s;
}

__global__ void __launch_bounds__(256) vq_init_k()
{
    int i = blockIdx.x * 256 + threadIdx.x;
    g_key[i] = ~0ULL;
    g_losspart[i] = 0.f;
}

// ---------------- VQ distance GEMM + argmin ----------------
// block computes 64 rows (2 batches) x 128 codebook entries, K=128
__global__ void __launch_bounds__(256) vq_gemm_k(const float* __restrict__ cb)
{
    int rbase = blockIdx.x * 64;
    int ebase = blockIdx.y * 128;
    int b0 = rbase >> 5;   // 2 batches per block

    __shared__ float Zs[32][68];    // Zs[k][r]
    __shared__ float Cs[32][132];   // Cs[k][e]
    __shared__ float cn[128];

    int tid = threadIdx.x;
    if (tid < 128) cn[tid] = g_cnorm[ebase + tid];
    int tx = tid & 15, ty = tid >> 4;
    int r0 = ty * 4, e0 = tx * 8;

    u64 acc2[4][4];
    #pragma unroll
    for (int i=0;i<4;i++)
        #pragma unroll
        for (int j=0;j<4;j++) acc2[i][j] = pack2(0.f,0.f);

    for (int kc = 0; kc < ED; kc += 32){
        #pragma unroll
        for (int it = 0; it < 2; it++){
            int i = tid + it*256;          // 0..511 float4s
            int brel = i >> 8;
            int t = (i & 255) * 4;         // contiguous within batch row
            float4 v = *(const float4*)(g_z + (b0+brel)*FLAT_Z + kc*32 + t);
            int k = t >> 5, s = t & 31;
            *(float4*)&Zs[k][brel*32 + s] = v;
        }
        #pragma unroll
        for (int it = 0; it < 4; it++){
            int i = tid + it*256;          // 0..1023 float4s
            int el = i >> 3; int kq = (i & 7) * 4;
            float4 v = *(const float4*)(cb + (ebase+el)*ED + kc + kq);
            Cs[kq+0][el]=v.x; Cs[kq+1][el]=v.y; Cs[kq+2][el]=v.z; Cs[kq+3][el]=v.w;
        }
        __syncthreads();
        #pragma unroll 4
        for (int k = 0; k < 32; k++){
            float4 a  = *(const float4*)&Zs[k][r0];
            float4 c0 = *(const float4*)&Cs[k][e0];
            float4 c1 = *(const float4*)&Cs[k][e0+4];
            u64 cp[4] = {pack2(c0.x,c0.y), pack2(c0.z,c0.w),
                         pack2(c1.x,c1.y), pack2(c1.z,c1.w)};
            float av[4] = {a.x,a.y,a.z,a.w};
            #pragma unroll
            for (int i=0;i<4;i++){
                u64 aa = pack2(av[i], av[i]);
                #pragma unroll
                for (int j=0;j<4;j++) acc2[i][j] = fma2(aa, cp[j], acc2[i][j]);
            }
        }
        __syncthreads();
    }

    #pragma unroll
    for (int i=0;i<4;i++){
        float best = 3.4e38f; int be = 0;
        #pragma unroll
        for (int j=0;j<4;j++){
            float d0, d1;
            unpack2(acc2[i][j], d0, d1);
            float da = cn[e0+2*j]   - 2.f*d0;
            float db = cn[e0+2*j+1] - 2.f*d1;
            if (da < best){ best = da; be = e0+2*j; }
            if (db < best){ best = db; be = e0+2*j+1; }
        }
        unsigned int bits = __float_as_uint(best);
        unsigned int key32 = (bits & 0x80000000u) ? ~bits : (bits | 0x80000000u);
        u64 key = ((u64)key32 << 32) | (unsigned)(ebase + be);
        atomicMin(&g_key[rbase + r0 + i], key);
    }
}

// ---------------- gather zq + per-row loss partial ----------------
__global__ void __launch_bounds__(128) vq_gather_k(const float* __restrict__ cb)
{
    int r = blockIdx.x;
    int b = r >> 5, s = r & 31;
    int e = (int)(unsigned)(g_key[r] & 0xFFFFFFFFULL);
    int k = threadIdx.x;
    float c = cb[e*ED + k];
    float z = g_z[b*FLAT_Z + k*32 + s];
    g_zq[b*FLAT_Z + k*32 + s] = c;
    float d = c - z; d = d * d;
    #pragma unroll
    for (int off = 16; off; off >>= 1) d += __shfl_down_sync(0xffffffffu, d, off);
    __shared__ float red[4];
    if ((threadIdx.x & 31) == 0) red[threadIdx.x >> 5] = d;
    __syncthreads();
    if (threadIdx.x == 0) g_losspart[r] = red[0]+red[1]+red[2]+red[3];
}

__global__ void __launch_bounds__(256) loss_reduce_k(float* __restrict__ dst)
{
    float s = 0.f;
    for (int i = threadIdx.x; i < NROWS; i += 256) s += g_losspart[i];
    __shared__ float rs[256];
    rs[threadIdx.x] = s;
    __syncthreads();
    for (int off = 128; off; off >>= 1){
        if (threadIdx.x < off) rs[threadIdx.x] += rs[threadIdx.x+off];
        __syncthreads();
    }
    if (threadIdx.x == 0) *dst = rs[0] * (1.25f / (float)(BB*FLAT_Z));
}

// ---------------- conv_out: out = W2 @ silu(concat(hout, himg)) + b2 ----------------
__global__ void __launch_bounds__(256) conv_out_k(const float* __restrict__ W,
                                                  const float* __restrict__ bias,
                                                  float* __restrict__ out)
{
    // grid: 64 b * 4 o-tiles * 4 p-tiles = 1024 blocks
    int bidx = blockIdx.x;
    int b  = bidx >> 4;
    int ot = (bidx >> 2) & 3;
    int pt = bidx & 3;
    int obase = ot * 64, pbase = pt * 64;

    __shared__ float Ws[2][16][68];
    __shared__ float Xs[2][16][68];

    int tid = threadIdx.x;
    int tx = tid & 15, ty = tid >> 4;
    int m0 = ty * 4, j0 = tx * 4;
    int lr = tid >> 2, kq = (tid & 3) * 4;
    int cl = tid >> 4, pl = (tid & 15) * 4;

    const float* Wp = W + (obase+lr)*CH + kq;

    u64 acc[4][2];
    #pragma unroll
    for (int i=0;i<4;i++){ acc[i][0]=pack2(0.f,0.f); acc[i][1]=acc[i][0]; }

    const int nt = CH/16;

    // prologue (ck = 0, always < NPH)
    float4 wv = *(const float4*)(Wp);
    const float* src0 = g_hout + b*FLAT_PH + cl*SP + pbase + pl;
    float4 xv = *(const float4*)(src0);
    Ws[0][kq+0][lr]=wv.x; Ws[0][kq+1][lr]=wv.y; Ws[0][kq+2][lr]=wv.z; Ws[0][kq+3][lr]=wv.w;
    Xs[0][cl][pl+0]=silu_f(xv.x); Xs[0][cl][pl+1]=silu_f(xv.y);
    Xs[0][cl][pl+2]=silu_f(xv.z); Xs[0][cl][pl+3]=silu_f(xv.w);
    __syncthreads();

    for (int t = 0; t < nt; t++){
        int cur = t & 1;
        bool more = (t+1) < nt;
        if (more){
            int ck = (t+1)*16;
            wv = *(const float4*)(Wp + ck);
            const float* src = (ck < NPH) ? (g_hout + b*FLAT_PH + ck*SP)
                                          : (g_himg + b*FLAT_PH + (ck-NPH)*SP);
            xv = *(const float4*)(src + cl*SP + pbase + pl);
        }
        #pragma unroll
        for (int k=0;k<16;k++){
            float4 a = *(const float4*)&Ws[cur][k][m0];
            float4 bv = *(const float4*)&Xs[cur][k][j0];
            fma_4x4(acc, a, bv);
        }
        if (more){
            int nx = cur^1;
            Ws[nx][kq+0][lr]=wv.x; Ws[nx][kq+1][lr]=wv.y; Ws[nx][kq+2][lr]=wv.z; Ws[nx][kq+3][lr]=wv.w;
            Xs[nx][cl][pl+0]=silu_f(xv.x); Xs[nx][cl][pl+1]=silu_f(xv.y);
            Xs[nx][cl][pl+2]=silu_f(xv.z); Xs[nx][cl][pl+3]=silu_f(xv.w);
        }
        __syncthreads();
    }

    #pragma unroll
    for (int i=0;i<4;i++){
        int o = obase + m0 + i;
        float bo = bias[o];
        float v0,v1,v2,v3;
        unpack2(acc[i][0], v0, v1); unpack2(acc[i][1], v2, v3);
        float4 ov; ov.x=v0+bo; ov.y=v1+bo; ov.z=v2+bo; ov.w=v3+bo;
        *(float4*)(out + (size_t)b*(C_OUT*SP) + o*SP + pbase + j0) = ov;
    }
}

// ---------------- launcher ----------------
extern "C" void kernel_launch(void* const* d_in, const int* in_sizes, int n_in,
                              void* d_out, int out_size)
{
    (void)in_sizes; (void)n_in;
    const float* x   = (const float*)d_in[0];
    const float* ciw = (const float*)d_in[1];
    const float* cib = (const float*)d_in[2];
    const float* lnw = (const float*)d_in[3];
    const float* lnb = (const float*)d_in[4];
    const float* miw = (const float*)d_in[5];
    const float* mib = (const float*)d_in[6];
    const float* cbk = (const float*)d_in[7];
    const float* mow = (const float*)d_in[8];
    const float* mob = (const float*)d_in[9];
    const float* cow = (const float*)d_in[10];
    const float* cob = (const float*)d_in[11];
    float* out = (float*)d_out;

    float *hn_p, *zp_p, *z_p, *zq_p, *hout_p;
    cudaGetSymbolAddress((void**)&hn_p,   g_hn);
    cudaGetSymbolAddress((void**)&zp_p,   g_zp);
    cudaGetSymbolAddress((void**)&z_p,    g_z);
    cudaGetSymbolAddress((void**)&zq_p,   g_zq);
    cudaGetSymbolAddress((void**)&hout_p, g_hout);

    conv_in_k<<<512, 256>>>(x, ciw, cib);
    ln_stats_k<<<64, 256>>>();
    ln_norm_k<<<dim3(64, 16), 256>>>(lnw, lnb);

    // mlp_in: split-K = 8 -> 512 blocks
    mlp_gemm_k<<<dim3(FLAT_Z/64, 8), 256>>>(hn_p, miw, zp_p,
                                            FLAT_PH, FLAT_Z, FLAT_PH/8);
    combine_k<<<BB*FLAT_Z/4/256, 256>>>(zp_p, z_p, mib, 8, BB*FLAT_Z, FLAT_Z);

    cnorm_k<<<NE/256, 256>>>(cbk);
    vq_init_k<<<NROWS/256, 256>>>();
    vq_gemm_k<<<dim3(NROWS/64, NE/128), 256>>>(cbk);
    vq_gather_k<<<NROWS, 128>>>(cbk);

    // mlp_out: split-K = 2 -> 512 blocks
    mlp_gemm_k<<<dim3(FLAT_PH/64, 2), 256>>>(zq_p, mow, zp_p,
                                             FLAT_Z, FLAT_PH, FLAT_Z/2);
    combine_k<<<BB*FLAT_PH/4/256, 256>>>(zp_p, hout_p, mob, 2, BB*FLAT_PH, FLAT_PH);

    conv_out_k<<<1024, 256>>>(cow, cob, out);

    if (out_size > OUT_ELEMS)
        loss_reduce_k<<<1, 256>>>(out + out_size - 1);
}

// round 6
// speedup vs baseline: 1.2563x; 1.2563x over previous
#include <cuda_runtime.h>

// ---------------- constants ----------------
#define BB 64
#define C_IN 256
#define CH 128
#define NPH 64
#define RR 16
#define SP 256          // R*R spatial
#define ED 128
#define CBQ 8
#define NL 4
#define NE 1024
#define C_OUT 256
#define FLAT_PH 16384   // NPH*R*R
#define FLAT_Z 4096     // ED*CB*NL
#define NROWS 2048      // B*CB*NL
#define OUT_ELEMS (BB*C_OUT*SP)   // 4194304

typedef unsigned long long u64;

#define DINLINE __device__ __forceinline__

DINLINE u64 pack2(float lo, float hi){ u64 r; asm("mov.b64 %0, {%1,%2};" : "=l"(r) : "f"(lo), "f"(hi)); return r; }
DINLINE void unpack2(u64 v, float &lo, float &hi){ asm("mov.b64 {%0,%1}, %2;" : "=f"(lo), "=f"(hi) : "l"(v)); }
DINLINE u64 fma2(u64 a, u64 b, u64 c){ u64 d; asm("fma.rn.f32x2 %0, %1, %2, %3;" : "=l"(d) : "l"(a), "l"(b), "l"(c)); return d; }
DINLINE float silu_f(float x){ return x / (1.f + __expf(-x)); }

// 4x4 microtile update using packed f32x2 FMAs (8 FFMA2 per k-step)
DINLINE void fma_4x4(u64 (&acc)[4][2], float4 a, float4 b){
    u64 b01 = pack2(b.x, b.y), b23 = pack2(b.z, b.w);
    u64 aa;
    aa = pack2(a.x, a.x); acc[0][0]=fma2(aa,b01,acc[0][0]); acc[0][1]=fma2(aa,b23,acc[0][1]);
    aa = pack2(a.y, a.y); acc[1][0]=fma2(aa,b01,acc[1][0]); acc[1][1]=fma2(aa,b23,acc[1][1]);
    aa = pack2(a.z, a.z); acc[2][0]=fma2(aa,b01,acc[2][0]); acc[2][1]=fma2(aa,b23,acc[2][1]);
    aa = pack2(a.w, a.w); acc[3][0]=fma2(aa,b01,acc[3][0]); acc[3][1]=fma2(aa,b23,acc[3][1]);
}

// ---------------- scratch (device globals; no allocs) ----------------
__device__ float g_hphylo[BB*FLAT_PH];   // conv_in phylo half (pre-LN)
__device__ float g_himg  [BB*FLAT_PH];   // conv_in img half (raw)
__device__ float g_hn    [BB*FLAT_PH];   // layernormed phylo
__device__ float g_stats [BB*2];         // mu, rstd per batch
__device__ float g_zp    [16*BB*FLAT_Z]; // split-K partials (16MB, shared by both MLPs)
__device__ float g_z     [BB*FLAT_Z];    // z
__device__ float g_zq    [BB*FLAT_Z];    // quantized z (codebook gather)
__device__ float g_hout  [BB*FLAT_PH];   // mlp_out output
__device__ float g_cnorm [NE];           // |codebook_e|^2
__device__ u64   g_key   [NROWS];        // packed (sortable_dist<<32)|idx
__device__ float g_losspart[NROWS];

// ---------------- conv_in: h = W @ silu(x) + b, split into phylo/img ----------------
__global__ void __launch_bounds__(256) conv_in_k(const float* __restrict__ x,
                                                 const float* __restrict__ W,
                                                 const float* __restrict__ bias)
{
    // grid: 64 b * 2 o-tiles * 4 p-tiles = 512 blocks
    int bidx = blockIdx.x;
    int b  = bidx >> 3;
    int ot = (bidx >> 2) & 1;
    int pt = bidx & 3;
    int obase = ot * 64, pbase = pt * 64;

    __shared__ float Ws[2][16][68];  // Ws[buf][c][o]
    __shared__ float Xs[2][16][68];  // Xs[buf][c][p] (silu applied)

    int tid = threadIdx.x;
    int tx = tid & 15, ty = tid >> 4;
    int m0 = ty * 4, j0 = tx * 4;          // m0 -> o, j0 -> p
    int lr = tid >> 2, kq = (tid & 3) * 4; // weight load mapping
    int cl = tid >> 4, pl = (tid & 15) * 4;// x load mapping

    const float* Wp = W + (obase+lr)*C_IN + kq;
    const float* Xp = x + b*(C_IN*SP) + cl*SP + pbase + pl;

    u64 acc[4][2];
    #pragma unroll
    for (int i=0;i<4;i++){ acc[i][0]=pack2(0.f,0.f); acc[i][1]=acc[i][0]; }

    const int nt = C_IN/16;
    float4 wv = *(const float4*)(Wp);
    float4 xv = *(const float4*)(Xp);
    Ws[0][kq+0][lr]=wv.x; Ws[0][kq+1][lr]=wv.y; Ws[0][kq+2][lr]=wv.z; Ws[0][kq+3][lr]=wv.w;
    Xs[0][cl][pl+0]=silu_f(xv.x); Xs[0][cl][pl+1]=silu_f(xv.y);
    Xs[0][cl][pl+2]=silu_f(xv.z); Xs[0][cl][pl+3]=silu_f(xv.w);
    __syncthreads();

    for (int t = 0; t < nt; t++){
        int cur = t & 1;
        bool more = (t+1) < nt;
        if (more){
            wv = *(const float4*)(Wp + (t+1)*16);
            xv = *(const float4*)(Xp + (t+1)*16*SP);
        }
        #pragma unroll
        for (int k=0;k<16;k++){
            float4 a = *(const float4*)&Ws[cur][k][m0];
            float4 bv = *(const float4*)&Xs[cur][k][j0];
            fma_4x4(acc, a, bv);
        }
        if (more){
            int nx = cur^1;
            Ws[nx][kq+0][lr]=wv.x; Ws[nx][kq+1][lr]=wv.y; Ws[nx][kq+2][lr]=wv.z; Ws[nx][kq+3][lr]=wv.w;
            Xs[nx][cl][pl+0]=silu_f(xv.x); Xs[nx][cl][pl+1]=silu_f(xv.y);
            Xs[nx][cl][pl+2]=silu_f(xv.z); Xs[nx][cl][pl+3]=silu_f(xv.w);
        }
        __syncthreads();
    }

    #pragma unroll
    for (int i=0;i<4;i++){
        int o = obase + m0 + i;
        float bo = bias[o];
        float v0,v1,v2,v3;
        unpack2(acc[i][0], v0, v1); unpack2(acc[i][1], v2, v3);
        float4 ov; ov.x=v0+bo; ov.y=v1+bo; ov.z=v2+bo; ov.w=v3+bo;
        float* dst = (o < NPH) ? (g_hphylo + b*FLAT_PH + o*SP)
                               : (g_himg   + b*FLAT_PH + (o-NPH)*SP);
        *(float4*)(dst + pbase + j0) = ov;
    }
}

// ---------------- layernorm stats (per batch over 16384 elems) ----------------
__global__ void __launch_bounds__(256) ln_stats_k()
{
    int b = blockIdx.x;
    const float4* p = (const float4*)(g_hphylo + b*FLAT_PH);
    float s = 0.f, s2 = 0.f;
    for (int i = threadIdx.x; i < FLAT_PH/4; i += 256){
        float4 v = p[i];
        s  += v.x + v.y + v.z + v.w;
        s2 += v.x*v.x + v.y*v.y + v.z*v.z + v.w*v.w;
    }
    __shared__ float rs[256], rq[256];
    rs[threadIdx.x] = s; rq[threadIdx.x] = s2;
    __syncthreads();
    for (int off = 128; off; off >>= 1){
        if (threadIdx.x < off){ rs[threadIdx.x]+=rs[threadIdx.x+off]; rq[threadIdx.x]+=rq[threadIdx.x+off]; }
        __syncthreads();
    }
    if (threadIdx.x == 0){
        float mu = rs[0] * (1.f/FLAT_PH);
        float var = rq[0] * (1.f/FLAT_PH) - mu*mu;
        g_stats[b*2+0] = mu;
        g_stats[b*2+1] = rsqrtf(var + 1e-5f);
    }
}

__global__ void __launch_bounds__(256) ln_norm_k(const float* __restrict__ lnw,
                                                 const float* __restrict__ lnb)
{
    int b = blockIdx.x;
    int base = blockIdx.y * 1024 + threadIdx.x * 4;
    float mu = g_stats[b*2+0], rstd = g_stats[b*2+1];
    float4 v = *(const float4*)(g_hphylo + b*FLAT_PH + base);
    float4 w = *(const float4*)(lnw + base);
    float4 bb = *(const float4*)(lnb + base);
    float4 o;
    o.x = (v.x-mu)*rstd*w.x + bb.x;
    o.y = (v.y-mu)*rstd*w.y + bb.y;
    o.z = (v.z-mu)*rstd*w.z + bb.z;
    o.w = (v.w-mu)*rstd*w.w + bb.w;
    *(float4*)(g_hn + b*FLAT_PH + base) = o;
}

// ---------------- skinny GEMM: C[64 x N] = A[64 x K] @ W[N x K]^T ----------------
// 64m x 128j tile, 4x8 microtile (16 FFMA2 : 3 LDS.128 per k-step).
// grid.x = N/128 tiles, grid.y = K splits (kchunk each). Split s writes C + s*64*N.
__global__ void __launch_bounds__(256) mlp_gemm_k(const float* __restrict__ A,
                                                  const float* __restrict__ W,
                                                  float* __restrict__ C,
                                                  int K, int N, int kchunk)
{
    __shared__ float As[2][16][68];    // As[buf][k][m]
    __shared__ float Bs[2][16][136];   // Bs[buf][k][j]
    int tid = threadIdx.x;
    int jbase = blockIdx.x * 128;
    int k0 = blockIdx.y * kchunk;
    float* Cout = C + (size_t)blockIdx.y * 64 * N;
    int tx = tid & 15, ty = tid >> 4;
    int m0 = ty * 4, j0 = tx * 8;
    int lr = tid >> 2, kq = (tid & 3) * 4;

    u64 acc[4][4];
    #pragma unroll
    for (int i=0;i<4;i++)
        #pragma unroll
        for (int j=0;j<4;j++) acc[i][j] = pack2(0.f,0.f);

    const float* Ap  = A + (size_t)lr * K + k0 + kq;
    const float* Wp0 = W + (size_t)(jbase + lr) * K + k0 + kq;
    const float* Wp1 = Wp0 + (size_t)64 * K;

    const int nt = kchunk >> 4;
    float4 av = *(const float4*)(Ap);
    float4 w0 = *(const float4*)(Wp0);
    float4 w1 = *(const float4*)(Wp1);
    As[0][kq+0][lr]=av.x; As[0][kq+1][lr]=av.y; As[0][kq+2][lr]=av.z; As[0][kq+3][lr]=av.w;
    Bs[0][kq+0][lr]=w0.x; Bs[0][kq+1][lr]=w0.y; Bs[0][kq+2][lr]=w0.z; Bs[0][kq+3][lr]=w0.w;
    Bs[0][kq+0][lr+64]=w1.x; Bs[0][kq+1][lr+64]=w1.y; Bs[0][kq+2][lr+64]=w1.z; Bs[0][kq+3][lr+64]=w1.w;
    __syncthreads();

    for (int t = 0; t < nt; t++){
        int cur = t & 1;
        bool more = (t+1) < nt;
        if (more){
            av = *(const float4*)(Ap  + (t+1)*16);
            w0 = *(const float4*)(Wp0 + (t+1)*16);
            w1 = *(const float4*)(Wp1 + (t+1)*16);
        }
        #pragma unroll
        for (int k=0;k<16;k++){
            float4 a  = *(const float4*)&As[cur][k][m0];
            float4 b0 = *(const float4*)&Bs[cur][k][j0];
            float4 b1 = *(const float4*)&Bs[cur][k][j0+4];
            u64 bp[4] = {pack2(b0.x,b0.y), pack2(b0.z,b0.w),
                         pack2(b1.x,b1.y), pack2(b1.z,b1.w)};
            float avr[4] = {a.x,a.y,a.z,a.w};
            #pragma unroll
            for (int i=0;i<4;i++){
                u64 aa = pack2(avr[i], avr[i]);
                #pragma unroll
                for (int j=0;j<4;j++) acc[i][j] = fma2(aa, bp[j], acc[i][j]);
            }
        }
        if (more){
            int nx = cur^1;
            As[nx][kq+0][lr]=av.x; As[nx][kq+1][lr]=av.y; As[nx][kq+2][lr]=av.z; As[nx][kq+3][lr]=av.w;
            Bs[nx][kq+0][lr]=w0.x; Bs[nx][kq+1][lr]=w0.y; Bs[nx][kq+2][lr]=w0.z; Bs[nx][kq+3][lr]=w0.w;
            Bs[nx][kq+0][lr+64]=w1.x; Bs[nx][kq+1][lr+64]=w1.y; Bs[nx][kq+2][lr+64]=w1.z; Bs[nx][kq+3][lr+64]=w1.w;
        }
        __syncthreads();
    }

    #pragma unroll
    for (int i=0;i<4;i++){
        float* row = Cout + (size_t)(m0+i)*N + jbase + j0;
        float v0,v1,v2,v3;
        unpack2(acc[i][0], v0, v1); unpack2(acc[i][1], v2, v3);
        float4 o0; o0.x=v0; o0.y=v1; o0.z=v2; o0.w=v3;
        *(float4*)(row) = o0;
        unpack2(acc[i][2], v0, v1); unpack2(acc[i][3], v2, v3);
        float4 o1; o1.x=v0; o1.y=v1; o1.z=v2; o1.w=v3;
        *(float4*)(row + 4) = o1;
    }
}

// ---------------- combine nsplit partials + bias ----------------
__global__ void __launch_bounds__(256) combine_k(const float* __restrict__ P,
                                                 float* __restrict__ out,
                                                 const float* __restrict__ bias,
                                                 int nsplit, int total, int N)
{
    int i = blockIdx.x * 256 + threadIdx.x;      // float4 index
    const float4* P4 = (const float4*)P;
    float4 s = P4[i];
    int stride = total >> 2;
    for (int sp = 1; sp < nsplit; sp++){
        float4 a = P4[i + sp*stride];
        s.x+=a.x; s.y+=a.y; s.z+=a.z; s.w+=a.w;
    }
    int j = (i * 4) & (N - 1);
    float4 bv = *(const float4*)(bias + j);
    s.x+=bv.x; s.y+=bv.y; s.z+=bv.z; s.w+=bv.w;
    ((float4*)out)[i] = s;
}

// ---------------- codebook norms ----------------
__global__ void __launch_bounds__(256) cnorm_k(const float* __restrict__ cb)
{
    int e = blockIdx.x * 256 + threadIdx.x;
    const float4* r = (const float4*)(cb + e*ED);
    float s = 0.f;
    #pragma unroll 8
    for (int i = 0; i < ED/4; i++){
        float4 v = r[i];
        s += v.x*v.x + v.y*v.y + v.z*v.z + v.w*v.w;
    }
    g_cnorm[e] = s;
}

__global__ void __launch_bounds__(256) vq_init_k()
{
    int i = blockIdx.x * 256 + threadIdx.x;
    g_key[i] = ~0ULL;
    g_losspart[i] = 0.f;
}

// ---------------- VQ distance GEMM + argmin ----------------
// block computes 64 rows (2 batches) x 128 codebook entries, K=128
__global__ void __launch_bounds__(256) vq_gemm_k(const float* __restrict__ cb)
{
    int rbase = blockIdx.x * 64;
    int ebase = blockIdx.y * 128;
    int b0 = rbase >> 5;   // 2 batches per block

    __shared__ float Zs[32][68];    // Zs[k][r]
    __shared__ float Cs[32][132];   // Cs[k][e]
    __shared__ float cn[128];

    int tid = threadIdx.x;
    if (tid < 128) cn[tid] = g_cnorm[ebase + tid];
    int tx = tid & 15, ty = tid >> 4;
    int r0 = ty * 4, e0 = tx * 8;

    u64 acc2[4][4];
    #pragma unroll
    for (int i=0;i<4;i++)
        #pragma unroll
        for (int j=0;j<4;j++) acc2[i][j] = pack2(0.f,0.f);

    for (int kc = 0; kc < ED; kc += 32){
        #pragma unroll
        for (int it = 0; it < 2; it++){
            int i = tid + it*256;          // 0..511 float4s
            int brel = i >> 8;
            int t = (i & 255) * 4;         // contiguous within batch row
            float4 v = *(const float4*)(g_z + (b0+brel)*FLAT_Z + kc*32 + t);
            int k = t >> 5, s = t & 31;
            *(float4*)&Zs[k][brel*32 + s] = v;
        }
        #pragma unroll
        for (int it = 0; it < 4; it++){
            int i = tid + it*256;          // 0..1023 float4s
            int el = i >> 3; int kq = (i & 7) * 4;
            float4 v = *(const float4*)(cb + (ebase+el)*ED + kc + kq);
            Cs[kq+0][el]=v.x; Cs[kq+1][el]=v.y; Cs[kq+2][el]=v.z; Cs[kq+3][el]=v.w;
        }
        __syncthreads();
        #pragma unroll 4
        for (int k = 0; k < 32; k++){
            float4 a  = *(const float4*)&Zs[k][r0];
            float4 c0 = *(const float4*)&Cs[k][e0];
            float4 c1 = *(const float4*)&Cs[k][e0+4];
            u64 cp[4] = {pack2(c0.x,c0.y), pack2(c0.z,c0.w),
                         pack2(c1.x,c1.y), pack2(c1.z,c1.w)};
            float av[4] = {a.x,a.y,a.z,a.w};
            #pragma unroll
            for (int i=0;i<4;i++){
                u64 aa = pack2(av[i], av[i]);
                #pragma unroll
                for (int j=0;j<4;j++) acc2[i][j] = fma2(aa, cp[j], acc2[i][j]);
            }
        }
        __syncthreads();
    }

    #pragma unroll
    for (int i=0;i<4;i++){
        float best = 3.4e38f; int be = 0;
        #pragma unroll
        for (int j=0;j<4;j++){
            float d0, d1;
            unpack2(acc2[i][j], d0, d1);
            float da = cn[e0+2*j]   - 2.f*d0;
            float db = cn[e0+2*j+1] - 2.f*d1;
            if (da < best){ best = da; be = e0+2*j; }
            if (db < best){ best = db; be = e0+2*j+1; }
        }
        unsigned int bits = __float_as_uint(best);
        unsigned int key32 = (bits & 0x80000000u) ? ~bits : (bits | 0x80000000u);
        u64 key = ((u64)key32 << 32) | (unsigned)(ebase + be);
        atomicMin(&g_key[rbase + r0 + i], key);
    }
}

// ---------------- gather zq + per-row loss partial ----------------
__global__ void __launch_bounds__(128) vq_gather_k(const float* __restrict__ cb)
{
    int r = blockIdx.x;
    int b = r >> 5, s = r & 31;
    int e = (int)(unsigned)(g_key[r] & 0xFFFFFFFFULL);
    int k = threadIdx.x;
    float c = cb[e*ED + k];
    float z = g_z[b*FLAT_Z + k*32 + s];
    g_zq[b*FLAT_Z + k*32 + s] = c;
    float d = c - z; d = d * d;
    #pragma unroll
    for (int off = 16; off; off >>= 1) d += __shfl_down_sync(0xffffffffu, d, off);
    __shared__ float red[4];
    if ((threadIdx.x & 31) == 0) red[threadIdx.x >> 5] = d;
    __syncthreads();
    if (threadIdx.x == 0) g_losspart[r] = red[0]+red[1]+red[2]+red[3];
}

__global__ void __launch_bounds__(256) loss_reduce_k(float* __restrict__ dst)
{
    float s = 0.f;
    for (int i = threadIdx.x; i < NROWS; i += 256) s += g_losspart[i];
    __shared__ float rs[256];
    rs[threadIdx.x] = s;
    __syncthreads();
    for (int off = 128; off; off >>= 1){
        if (threadIdx.x < off) rs[threadIdx.x] += rs[threadIdx.x+off];
        __syncthreads();
    }
    if (threadIdx.x == 0) *dst = rs[0] * (1.25f / (float)(BB*FLAT_Z));
}

// ---------------- conv_out: out = W2 @ silu(concat(hout, himg)) + b2 ----------------
__global__ void __launch_bounds__(256) conv_out_k(const float* __restrict__ W,
                                                  const float* __restrict__ bias,
                                                  float* __restrict__ out)
{
    // grid: 64 b * 4 o-tiles * 4 p-tiles = 1024 blocks
    int bidx = blockIdx.x;
    int b  = bidx >> 4;
    int ot = (bidx >> 2) & 3;
    int pt = bidx & 3;
    int obase = ot * 64, pbase = pt * 64;

    __shared__ float Ws[2][16][68];
    __shared__ float Xs[2][16][68];

    int tid = threadIdx.x;
    int tx = tid & 15, ty = tid >> 4;
    int m0 = ty * 4, j0 = tx * 4;
    int lr = tid >> 2, kq = (tid & 3) * 4;
    int cl = tid >> 4, pl = (tid & 15) * 4;

    const float* Wp = W + (obase+lr)*CH + kq;

    u64 acc[4][2];
    #pragma unroll
    for (int i=0;i<4;i++){ acc[i][0]=pack2(0.f,0.f); acc[i][1]=acc[i][0]; }

    const int nt = CH/16;

    // prologue (ck = 0, always < NPH)
    float4 wv = *(const float4*)(Wp);
    const float* src0 = g_hout + b*FLAT_PH + cl*SP + pbase + pl;
    float4 xv = *(const float4*)(src0);
    Ws[0][kq+0][lr]=wv.x; Ws[0][kq+1][lr]=wv.y; Ws[0][kq+2][lr]=wv.z; Ws[0][kq+3][lr]=wv.w;
    Xs[0][cl][pl+0]=silu_f(xv.x); Xs[0][cl][pl+1]=silu_f(xv.y);
    Xs[0][cl][pl+2]=silu_f(xv.z); Xs[0][cl][pl+3]=silu_f(xv.w);
    __syncthreads();

    for (int t = 0; t < nt; t++){
        int cur = t & 1;
        bool more = (t+1) < nt;
        if (more){
            int ck = (t+1)*16;
            wv = *(const float4*)(Wp + ck);
            const float* src = (ck < NPH) ? (g_hout + b*FLAT_PH + ck*SP)
                                          : (g_himg + b*FLAT_PH + (ck-NPH)*SP);
            xv = *(const float4*)(src + cl*SP + pbase + pl);
        }
        #pragma unroll
        for (int k=0;k<16;k++){
            float4 a = *(const float4*)&Ws[cur][k][m0];
            float4 bv = *(const float4*)&Xs[cur][k][j0];
            fma_4x4(acc, a, bv);
        }
        if (more){
            int nx = cur^1;
            Ws[nx][kq+0][lr]=wv.x; Ws[nx][kq+1][lr]=wv.y; Ws[nx][kq+2][lr]=wv.z; Ws[nx][kq+3][lr]=wv.w;
            Xs[nx][cl][pl+0]=silu_f(xv.x); Xs[nx][cl][pl+1]=silu_f(xv.y);
            Xs[nx][cl][pl+2]=silu_f(xv.z); Xs[nx][cl][pl+3]=silu_f(xv.w);
        }
        __syncthreads();
    }

    #pragma unroll
    for (int i=0;i<4;i++){
        int o = obase + m0 + i;
        float bo = bias[o];
        float v0,v1,v2,v3;
        unpack2(acc[i][0], v0, v1); unpack2(acc[i][1], v2, v3);
        float4 ov; ov.x=v0+bo; ov.y=v1+bo; ov.z=v2+bo; ov.w=v3+bo;
        *(float4*)(out + (size_t)b*(C_OUT*SP) + o*SP + pbase + j0) = ov;
    }
}

// ---------------- launcher ----------------
extern "C" void kernel_launch(void* const* d_in, const int* in_sizes, int n_in,
                              void* d_out, int out_size)
{
    (void)in_sizes; (void)n_in;
    const float* x   = (const float*)d_in[0];
    const float* ciw = (const float*)d_in[1];
    const float* cib = (const float*)d_in[2];
    const float* lnw = (const float*)d_in[3];
    const float* lnb = (const float*)d_in[4];
    const float* miw = (const float*)d_in[5];
    const float* mib = (const float*)d_in[6];
    const float* cbk = (const float*)d_in[7];
    const float* mow = (const float*)d_in[8];
    const float* mob = (const float*)d_in[9];
    const float* cow = (const float*)d_in[10];
    const float* cob = (const float*)d_in[11];
    float* out = (float*)d_out;

    float *hn_p, *zp_p, *z_p, *zq_p, *hout_p;
    cudaGetSymbolAddress((void**)&hn_p,   g_hn);
    cudaGetSymbolAddress((void**)&zp_p,   g_zp);
    cudaGetSymbolAddress((void**)&z_p,    g_z);
    cudaGetSymbolAddress((void**)&zq_p,   g_zq);
    cudaGetSymbolAddress((void**)&hout_p, g_hout);

    conv_in_k<<<512, 256>>>(x, ciw, cib);
    ln_stats_k<<<64, 256>>>();
    ln_norm_k<<<dim3(64, 16), 256>>>(lnw, lnb);

    // mlp_in: 32 j-tiles x split-K 16 -> 512 blocks, kchunk 1024
    mlp_gemm_k<<<dim3(FLAT_Z/128, 16), 256>>>(hn_p, miw, zp_p,
                                              FLAT_PH, FLAT_Z, FLAT_PH/16);
    combine_k<<<BB*FLAT_Z/4/256, 256>>>(zp_p, z_p, mib, 16, BB*FLAT_Z, FLAT_Z);

    cnorm_k<<<NE/256, 256>>>(cbk);
    vq_init_k<<<NROWS/256, 256>>>();
    vq_gemm_k<<<dim3(NROWS/64, NE/128), 256>>>(cbk);
    vq_gather_k<<<NROWS, 128>>>(cbk);

    // mlp_out: 128 j-tiles x split-K 4 -> 512 blocks, kchunk 1024
    mlp_gemm_k<<<dim3(FLAT_PH/128, 4), 256>>>(zq_p, mow, zp_p,
                                              FLAT_Z, FLAT_PH, FLAT_Z/4);
    combine_k<<<BB*FLAT_PH/4/256, 256>>>(zp_p, hout_p, mob, 4, BB*FLAT_PH, FLAT_PH);

    conv_out_k<<<1024, 256>>>(cow, cob, out);

    if (out_size > OUT_ELEMS)
        loss_reduce_k<<<1, 256>>>(out + out_size - 1);
}

// round 9
// speedup vs baseline: 3.1552x; 2.5116x over previous
#include <cuda_runtime.h>
#include <cuda_bf16.h>
#include <cstdint>

// ---------------- constants ----------------
#define BB 64
#define C_IN 256
#define CH 128
#define NPH 64
#define SP 256          // R*R spatial
#define ED 128
#define NE 1024
#define C_OUT 256
#define FLAT_PH 16384   // NPH*R*R
#define FLAT_Z 4096     // ED*CB*NL
#define NROWS 2048      // B*CB*NL
#define OUT_ELEMS (BB*C_OUT*SP)   // 4194304

typedef unsigned long long u64;
typedef unsigned int u32;

#define DINLINE __device__ __forceinline__

DINLINE u64 pack2(float lo, float hi){ u64 r; asm("mov.b64 %0, {%1,%2};" : "=l"(r) : "f"(lo), "f"(hi)); return r; }
DINLINE void unpack2(u64 v, float &lo, float &hi){ asm("mov.b64 {%0,%1}, %2;" : "=f"(lo), "=f"(hi) : "l"(v)); }
DINLINE u64 fma2(u64 a, u64 b, u64 c){ u64 d; asm("fma.rn.f32x2 %0, %1, %2, %3;" : "=l"(d) : "l"(a), "l"(b), "l"(c)); return d; }
DINLINE float silu_f(float x){ return x / (1.f + __expf(-x)); }

// 4x4 microtile update using packed f32x2 FMAs
DINLINE void fma_4x4(u64 (&acc)[4][2], float4 a, float4 b){
    u64 b01 = pack2(b.x, b.y), b23 = pack2(b.z, b.w);
    u64 aa;
    aa = pack2(a.x, a.x); acc[0][0]=fma2(aa,b01,acc[0][0]); acc[0][1]=fma2(aa,b23,acc[0][1]);
    aa = pack2(a.y, a.y); acc[1][0]=fma2(aa,b01,acc[1][0]); acc[1][1]=fma2(aa,b23,acc[1][1]);
    aa = pack2(a.z, a.z); acc[2][0]=fma2(aa,b01,acc[2][0]); acc[2][1]=fma2(aa,b23,acc[2][1]);
    aa = pack2(a.w, a.w); acc[3][0]=fma2(aa,b01,acc[3][0]); acc[3][1]=fma2(aa,b23,acc[3][1]);
}

// ---- bf16 split of a pair of floats: h = bf16x2(hi parts), l = bf16x2(residuals) ----
DINLINE void split2(float x, float y, u32 &h, u32 &l){
    __nv_bfloat16 hx = __float2bfloat16(x), hy = __float2bfloat16(y);
    float rx = x - __bfloat162float(hx);
    float ry = y - __bfloat162float(hy);
    __nv_bfloat16 lx = __float2bfloat16(rx), ly = __float2bfloat16(ry);
    h = (u32)__bfloat16_as_ushort(hx) | ((u32)__bfloat16_as_ushort(hy) << 16);
    l = (u32)__bfloat16_as_ushort(lx) | ((u32)__bfloat16_as_ushort(ly) << 16);
}

DINLINE uint32_t smem_u32(const void* p){
    uint32_t a;
    asm("{ .reg .u64 t; cvta.to.shared.u64 t, %1; cvt.u32.u64 %0, t; }" : "=r"(a) : "l"(p));
    return a;
}
DINLINE void sts64(uint32_t addr, u32 a, u32 b){
    asm volatile("st.shared.v2.b32 [%0], {%1,%2};" :: "r"(addr), "r"(a), "r"(b) : "memory");
}
DINLINE void sts32(uint32_t addr, u32 a){
    asm volatile("st.shared.b32 [%0], %1;" :: "r"(addr), "r"(a) : "memory");
}
DINLINE u32 lds32(uint32_t addr){
    u32 v; asm volatile("ld.shared.b32 %0, [%1];" : "=r"(v) : "r"(addr)); return v;
}
DINLINE void ldsm4(u32 (&r)[4], uint32_t addr){
    asm volatile("ldmatrix.sync.aligned.m8n8.x4.shared.b16 {%0,%1,%2,%3}, [%4];"
                 : "=r"(r[0]), "=r"(r[1]), "=r"(r[2]), "=r"(r[3]) : "r"(addr));
}
DINLINE void mma_bf16(float (&d)[4], const u32 (&a)[4], const u32 (&b)[2]){
    asm volatile("mma.sync.aligned.m16n8k16.row.col.f32.bf16.bf16.f32 "
                 "{%0,%1,%2,%3}, {%4,%5,%6,%7}, {%8,%9}, {%0,%1,%2,%3};"
                 : "+f"(d[0]), "+f"(d[1]), "+f"(d[2]), "+f"(d[3])
                 : "r"(a[0]), "r"(a[1]), "r"(a[2]), "r"(a[3]), "r"(b[0]), "r"(b[1]));
}

// ---------------- scratch (device globals; no allocs) ----------------
__device__ float g_hphylo[BB*FLAT_PH];   // conv_in phylo half (pre-LN)
__device__ float g_himg  [BB*FLAT_PH];   // conv_in img half (raw)
__device__ float g_stats [BB*2];         // mu, rstd per batch
__device__ float g_zp    [8*BB*FLAT_Z];  // split-K partials (8MB, shared by both MLPs)
__device__ float g_z     [BB*FLAT_Z];    // z
__device__ float g_zq    [BB*FLAT_Z];    // quantized z (fp32)
__device__ float g_hout  [BB*FLAT_PH];   // mlp_out output
__device__ float g_cnorm [NE];           // |codebook_e|^2
__device__ u64   g_key   [NROWS];        // packed (sortable_dist<<32)|idx
__device__ float g_losspart[NROWS];
// packed activations for mma GEMMs: word w at [k2][batch], bf16x2 (k even in low half)
__device__ u32   g_aph[(FLAT_PH/2)*BB];  // hn hi
__device__ u32   g_apl[(FLAT_PH/2)*BB];  // hn lo
__device__ u32   g_zph[(FLAT_Z/2)*BB];   // zq hi
__device__ u32   g_zpl[(FLAT_Z/2)*BB];   // zq lo

// ---------------- conv_in ----------------
__global__ void __launch_bounds__(256) conv_in_k(const float* __restrict__ x,
                                                 const float* __restrict__ W,
                                                 const float* __restrict__ bias)
{
    int bidx = blockIdx.x;
    int b  = bidx >> 3;
    int ot = (bidx >> 2) & 1;
    int pt = bidx & 3;
    int obase = ot * 64, pbase = pt * 64;

    __shared__ float Ws[2][16][68];
    __shared__ float Xs[2][16][68];

    int tid = threadIdx.x;
    int tx = tid & 15, ty = tid >> 4;
    int m0 = ty * 4, j0 = tx * 4;
    int lr = tid >> 2, kq = (tid & 3) * 4;
    int cl = tid >> 4, pl = (tid & 15) * 4;

    const float* Wp = W + (obase+lr)*C_IN + kq;
    const float* Xp = x + b*(C_IN*SP) + cl*SP + pbase + pl;

    u64 acc[4][2];
    #pragma unroll
    for (int i=0;i<4;i++){ acc[i][0]=pack2(0.f,0.f); acc[i][1]=acc[i][0]; }

    const int nt = C_IN/16;
    float4 wv = *(const float4*)(Wp);
    float4 xv = *(const float4*)(Xp);
    Ws[0][kq+0][lr]=wv.x; Ws[0][kq+1][lr]=wv.y; Ws[0][kq+2][lr]=wv.z; Ws[0][kq+3][lr]=wv.w;
    Xs[0][cl][pl+0]=silu_f(xv.x); Xs[0][cl][pl+1]=silu_f(xv.y);
    Xs[0][cl][pl+2]=silu_f(xv.z); Xs[0][cl][pl+3]=silu_f(xv.w);
    __syncthreads();

    for (int t = 0; t < nt; t++){
        int cur = t & 1;
        bool more = (t+1) < nt;
        if (more){
            wv = *(const float4*)(Wp + (t+1)*16);
            xv = *(const float4*)(Xp + (t+1)*16*SP);
        }
        #pragma unroll
        for (int k=0;k<16;k++){
            float4 a = *(const float4*)&Ws[cur][k][m0];
            float4 bv = *(const float4*)&Xs[cur][k][j0];
            fma_4x4(acc, a, bv);
        }
        if (more){
            int nx = cur^1;
            Ws[nx][kq+0][lr]=wv.x; Ws[nx][kq+1][lr]=wv.y; Ws[nx][kq+2][lr]=wv.z; Ws[nx][kq+3][lr]=wv.w;
            Xs[nx][cl][pl+0]=silu_f(xv.x); Xs[nx][cl][pl+1]=silu_f(xv.y);
            Xs[nx][cl][pl+2]=silu_f(xv.z); Xs[nx][cl][pl+3]=silu_f(xv.w);
        }
        __syncthreads();
    }

    #pragma unroll
    for (int i=0;i<4;i++){
        int o = obase + m0 + i;
        float bo = bias[o];
        float v0,v1,v2,v3;
        unpack2(acc[i][0], v0, v1); unpack2(acc[i][1], v2, v3);
        float4 ov; ov.x=v0+bo; ov.y=v1+bo; ov.z=v2+bo; ov.w=v3+bo;
        float* dst = (o < NPH) ? (g_hphylo + b*FLAT_PH + o*SP)
                               : (g_himg   + b*FLAT_PH + (o-NPH)*SP);
        *(float4*)(dst + pbase + j0) = ov;
    }
}

// ---------------- layernorm stats ----------------
__global__ void __launch_bounds__(256) ln_stats_k()
{
    int b = blockIdx.x;
    const float4* p = (const float4*)(g_hphylo + b*FLAT_PH);
    float s = 0.f, s2 = 0.f;
    for (int i = threadIdx.x; i < FLAT_PH/4; i += 256){
        float4 v = p[i];
        s  += v.x + v.y + v.z + v.w;
        s2 += v.x*v.x + v.y*v.y + v.z*v.z + v.w*v.w;
    }
    __shared__ float rs[256], rq[256];
    rs[threadIdx.x] = s; rq[threadIdx.x] = s2;
    __syncthreads();
    for (int off = 128; off; off >>= 1){
        if (threadIdx.x < off){ rs[threadIdx.x]+=rs[threadIdx.x+off]; rq[threadIdx.x]+=rq[threadIdx.x+off]; }
        __syncthreads();
    }
    if (threadIdx.x == 0){
        float mu = rs[0] * (1.f/FLAT_PH);
        float var = rq[0] * (1.f/FLAT_PH) - mu*mu;
        g_stats[b*2+0] = mu;
        g_stats[b*2+1] = rsqrtf(var + 1e-5f);
    }
}

// layernorm apply + bf16 hi/lo pack -> g_aph/g_apl ([k2][batch] layout)
__global__ void __launch_bounds__(256) ln_norm_k(const float* __restrict__ lnw,
                                                 const float* __restrict__ lnb)
{
    int b = blockIdx.x;
    int base = blockIdx.y * 1024 + threadIdx.x * 4;
    float mu = g_stats[b*2+0], rstd = g_stats[b*2+1];
    float4 v = *(const float4*)(g_hphylo + b*FLAT_PH + base);
    float4 w = *(const float4*)(lnw + base);
    float4 bb = *(const float4*)(lnb + base);
    float o0 = (v.x-mu)*rstd*w.x + bb.x;
    float o1 = (v.y-mu)*rstd*w.y + bb.y;
    float o2 = (v.z-mu)*rstd*w.z + bb.z;
    float o3 = (v.w-mu)*rstd*w.w + bb.w;
    u32 h0,l0,h1,l1;
    split2(o0,o1,h0,l0);
    split2(o2,o3,h1,l1);
    int k2 = base >> 1;
    g_aph[(size_t)k2*BB + b]     = h0;
    g_aph[(size_t)(k2+1)*BB + b] = h1;
    g_apl[(size_t)k2*BB + b]     = l0;
    g_apl[(size_t)(k2+1)*BB + b] = l1;
}

// ---------------- mma.sync bf16x3 GEMM ----------------
// C[64 x N] = A[64 x K] @ W[N x K]^T. grid.x = N/128 j-tiles, grid.y = split-K.
// Per CTA: 128 j x 64 batch, k-chunk 32, double-buffered smem.
// smem buffer layout (bytes): Wh[128][40]b16 @0 (10240) | Wl @10240 | Ah[16][72]u32 @20480 | Al @25088; BUF=29696
#define MMA_BUF 29696
#define MMA_SMEM (2*MMA_BUF)

__global__ void __launch_bounds__(256, 2)
mlp_mma_k(const u32* __restrict__ Aph, const u32* __restrict__ Apl,
          const float* __restrict__ W, float* __restrict__ C,
          int K, int N, int kchunk)
{
    extern __shared__ char dsm[];
    uint32_t sb = smem_u32(dsm);

    int tid = threadIdx.x;
    int lane = tid & 31, wid = tid >> 5;
    int g = lane >> 2, tig = lane & 3;
    int jw = (wid & 3) * 32, bw = (wid >> 2) * 32;
    int jbase = blockIdx.x * 128;
    int k0 = blockIdx.y * kchunk;
    float* Cout = C + (size_t)blockIdx.y * 64 * N;

    float dacc[2][4][4];
    #pragma unroll
    for (int m=0;m<2;m++)
        #pragma unroll
        for (int n=0;n<4;n++)
            #pragma unroll
            for (int q=0;q<4;q++) dacc[m][n][q] = 0.f;

    const int nch = kchunk >> 5;

    float4 wreg[4]; u32 ahreg[4], alreg[4];

    // prologue: load chunk 0
    #pragma unroll
    for (int i=0;i<4;i++){ int idx=tid+256*i; int r=idx>>3, s=idx&7;
        wreg[i] = *(const float4*)(W + (size_t)(jbase+r)*K + k0 + s*4); }
    {
        int kb = (k0>>1);
        #pragma unroll
        for (int i=0;i<4;i++){ int idx=tid+256*i; int k2=idx>>6, b=idx&63;
            ahreg[i] = Aph[(size_t)(kb+k2)*BB + b];
            alreg[i] = Apl[(size_t)(kb+k2)*BB + b]; }
    }
    // store chunk 0 into buffer 0
    {
        uint32_t Bb = sb;
        #pragma unroll
        for (int i=0;i<4;i++){ int idx=tid+256*i; int r=idx>>3, s=idx&7;
            u32 h0,l0,h1,l1;
            split2(wreg[i].x, wreg[i].y, h0, l0);
            split2(wreg[i].z, wreg[i].w, h1, l1);
            uint32_t off = r*80 + s*8;
            sts64(Bb + off, h0, h1);
            sts64(Bb + 10240 + off, l0, l1);
        }
        #pragma unroll
        for (int i=0;i<4;i++){ int idx=tid+256*i; int k2=idx>>6, b=idx&63;
            uint32_t off = (u32)(k2*72 + b)*4;
            sts32(Bb + 20480 + off, ahreg[i]);
            sts32(Bb + 25088 + off, alreg[i]);
        }
    }
    __syncthreads();

    for (int ch = 0; ch < nch; ch++){
        int cur = ch & 1;
        bool more = (ch+1) < nch;
        if (more){
            int kk = k0 + (ch+1)*32;
            #pragma unroll
            for (int i=0;i<4;i++){ int idx=tid+256*i; int r=idx>>3, s=idx&7;
                wreg[i] = *(const float4*)(W + (size_t)(jbase+r)*K + kk + s*4); }
            int kb = (kk>>1);
            #pragma unroll
            for (int i=0;i<4;i++){ int idx=tid+256*i; int k2=idx>>6, b=idx&63;
                ahreg[i] = Aph[(size_t)(kb+k2)*BB + b];
                alreg[i] = Apl[(size_t)(kb+k2)*BB + b]; }
        }

        // compute on buffer cur
        {
            uint32_t Bb = sb + cur*MMA_BUF;
            int lrow = ((lane>>3)&1)*8 + (lane&7);
            int lkc  = (lane>>4)*8;
            #pragma unroll
            for (int ks = 0; ks < 2; ks++){
                u32 wh[2][4], wl[2][4];
                #pragma unroll
                for (int m=0;m<2;m++){
                    uint32_t ad = Bb + (u32)((jw + m*16 + lrow)*40 + lkc + ks*16)*2;
                    ldsm4(wh[m], ad);
                    ldsm4(wl[m], ad + 10240);
                }
                u32 bh[4][2], bl[4][2];
                #pragma unroll
                for (int nf=0;nf<4;nf++){
                    uint32_t a0 = Bb + 20480 + (u32)((ks*8+tig)*72 + bw + nf*8 + g)*4;
                    bh[nf][0] = lds32(a0);
                    bh[nf][1] = lds32(a0 + 4*72*4);
                    bl[nf][0] = lds32(a0 + 4608);
                    bl[nf][1] = lds32(a0 + 4608 + 4*72*4);
                }
                #pragma unroll
                for (int m=0;m<2;m++)
                    #pragma unroll
                    for (int nf=0;nf<4;nf++){
                        mma_bf16(dacc[m][nf], wh[m], bh[nf]);
                        mma_bf16(dacc[m][nf], wh[m], bl[nf]);
                        mma_bf16(dacc[m][nf], wl[m], bh[nf]);
                    }
            }
        }

        if (more){
            uint32_t Bb = sb + (cur^1)*MMA_BUF;
            #pragma unroll
            for (int i=0;i<4;i++){ int idx=tid+256*i; int r=idx>>3, s=idx&7;
                u32 h0,l0,h1,l1;
                split2(wreg[i].x, wreg[i].y, h0, l0);
                split2(wreg[i].z, wreg[i].w, h1, l1);
                uint32_t off = r*80 + s*8;
                sts64(Bb + off, h0, h1);
                sts64(Bb + 10240 + off, l0, l1);
            }
            #pragma unroll
            for (int i=0;i<4;i++){ int idx=tid+256*i; int k2=idx>>6, b=idx&63;
                uint32_t off = (u32)(k2*72 + b)*4;
                sts32(Bb + 20480 + off, ahreg[i]);
                sts32(Bb + 25088 + off, alreg[i]);
            }
        }
        __syncthreads();
    }

    // epilogue: write D fragments (rows j, cols batch) to C[b*N + j]
    #pragma unroll
    for (int m=0;m<2;m++){
        int j = jbase + jw + m*16 + g;
        #pragma unroll
        for (int nf=0;nf<4;nf++){
            int b = bw + nf*8 + 2*tig;
            Cout[(size_t)b*N + j]         = dacc[m][nf][0];
            Cout[(size_t)(b+1)*N + j]     = dacc[m][nf][1];
            Cout[(size_t)b*N + j + 8]     = dacc[m][nf][2];
            Cout[(size_t)(b+1)*N + j + 8] = dacc[m][nf][3];
        }
    }
}

// ---------------- combine nsplit partials + bias ----------------
__global__ void __launch_bounds__(256) combine_k(const float* __restrict__ P,
                                                 float* __restrict__ out,
                                                 const float* __restrict__ bias,
                                                 int nsplit, int total, int N)
{
    int i = blockIdx.x * 256 + threadIdx.x;
    const float4* P4 = (const float4*)P;
    float4 s = P4[i];
    int stride = total >> 2;
    for (int sp = 1; sp < nsplit; sp++){
        float4 a = P4[i + sp*stride];
        s.x+=a.x; s.y+=a.y; s.z+=a.z; s.w+=a.w;
    }
    int j = (i * 4) & (N - 1);
    float4 bv = *(const float4*)(bias + j);
    s.x+=bv.x; s.y+=bv.y; s.z+=bv.z; s.w+=bv.w;
    ((float4*)out)[i] = s;
}

// ---------------- codebook norms ----------------
__global__ void __launch_bounds__(256) cnorm_k(const float* __restrict__ cb)
{
    int e = blockIdx.x * 256 + threadIdx.x;
    const float4* r = (const float4*)(cb + e*ED);
    float s = 0.f;
    #pragma unroll 8
    for (int i = 0; i < ED/4; i++){
        float4 v = r[i];
        s += v.x*v.x + v.y*v.y + v.z*v.z + v.w*v.w;
    }
    g_cnorm[e] = s;
}

__global__ void __launch_bounds__(256) vq_init_k()
{
    int i = blockIdx.x * 256 + threadIdx.x;
    g_key[i] = ~0ULL;
    g_losspart[i] = 0.f;
}

// ---------------- VQ distance GEMM + argmin ----------------
__global__ void __launch_bounds__(256) vq_gemm_k(const float* __restrict__ cb)
{
    int rbase = blockIdx.x * 64;
    int ebase = blockIdx.y * 128;
    int b0 = rbase >> 5;

    __shared__ float Zs[32][68];
    __shared__ float Cs[32][132];
    __shared__ float cn[128];

    int tid = threadIdx.x;
    if (tid < 128) cn[tid] = g_cnorm[ebase + tid];
    int tx = tid & 15, ty = tid >> 4;
    int r0 = ty * 4, e0 = tx * 8;

    u64 acc2[4][4];
    #pragma unroll
    for (int i=0;i<4;i++)
        #pragma unroll
        for (int j=0;j<4;j++) acc2[i][j] = pack2(0.f,0.f);

    for (int kc = 0; kc < ED; kc += 32){
        #pragma unroll
        for (int it = 0; it < 2; it++){
            int i = tid + it*256;
            int brel = i >> 8;
            int t = (i & 255) * 4;
            float4 v = *(const float4*)(g_z + (b0+brel)*FLAT_Z + kc*32 + t);
            int k = t >> 5, s = t & 31;
            *(float4*)&Zs[k][brel*32 + s] = v;
        }
        #pragma unroll
        for (int it = 0; it < 4; it++){
            int i = tid + it*256;
            int el = i >> 3; int kq = (i & 7) * 4;
            float4 v = *(const float4*)(cb + (ebase+el)*ED + kc + kq);
            Cs[kq+0][el]=v.x; Cs[kq+1][el]=v.y; Cs[kq+2][el]=v.z; Cs[kq+3][el]=v.w;
        }
        __syncthreads();
        #pragma unroll 4
        for (int k = 0; k < 32; k++){
            float4 a  = *(const float4*)&Zs[k][r0];
            float4 c0 = *(const float4*)&Cs[k][e0];
            float4 c1 = *(const float4*)&Cs[k][e0+4];
            u64 cp[4] = {pack2(c0.x,c0.y), pack2(c0.z,c0.w),
                         pack2(c1.x,c1.y), pack2(c1.z,c1.w)};
            float av[4] = {a.x,a.y,a.z,a.w};
            #pragma unroll
            for (int i=0;i<4;i++){
                u64 aa = pack2(av[i], av[i]);
                #pragma unroll
                for (int j=0;j<4;j++) acc2[i][j] = fma2(aa, cp[j], acc2[i][j]);
            }
        }
        __syncthreads();
    }

    #pragma unroll
    for (int i=0;i<4;i++){
        float best = 3.4e38f; int be = 0;
        #pragma unroll
        for (int j=0;j<4;j++){
            float d0, d1;
            unpack2(acc2[i][j], d0, d1);
            float da = cn[e0+2*j]   - 2.f*d0;
            float db = cn[e0+2*j+1] - 2.f*d1;
            if (da < best){ best = da; be = e0+2*j; }
            if (db < best){ best = db; be = e0+2*j+1; }
        }
        unsigned int bits = __float_as_uint(best);
        unsigned int key32 = (bits & 0x80000000u) ? ~bits : (bits | 0x80000000u);
        u64 key = ((u64)key32 << 32) | (unsigned)(ebase + be);
        atomicMin(&g_key[rbase + r0 + i], key);
    }
}

// ---------------- gather zq (fp32) + per-row loss partial ----------------
__global__ void __launch_bounds__(128) vq_gather_k(const float* __restrict__ cb)
{
    int r = blockIdx.x;
    int b = r >> 5, s = r & 31;
    int e = (int)(unsigned)(g_key[r] & 0xFFFFFFFFULL);
    int k = threadIdx.x;
    float c = cb[e*ED + k];
    float z = g_z[b*FLAT_Z + k*32 + s];
    g_zq[b*FLAT_Z + k*32 + s] = c;
    float d = c - z; d = d * d;
    #pragma unroll
    for (int off = 16; off; off >>= 1) d += __shfl_down_sync(0xffffffffu, d, off);
    __shared__ float red[4];
    if ((threadIdx.x & 31) == 0) red[threadIdx.x >> 5] = d;
    __syncthreads();
    if (threadIdx.x == 0) g_losspart[r] = red[0]+red[1]+red[2]+red[3];
}

// pack zq into bf16 hi/lo [k2][batch] words
__global__ void __launch_bounds__(256) z_pack_k()
{
    int b = blockIdx.x;
    for (int w = threadIdx.x; w < FLAT_Z/2; w += 256){
        float f0 = g_zq[b*FLAT_Z + 2*w];
        float f1 = g_zq[b*FLAT_Z + 2*w + 1];
        u32 h, l;
        split2(f0, f1, h, l);
        g_zph[(size_t)w*BB + b] = h;
        g_zpl[(size_t)w*BB + b] = l;
    }
}

__global__ void __launch_bounds__(256) loss_reduce_k(float* __restrict__ dst)
{
    float s = 0.f;
    for (int i = threadIdx.x; i < NROWS; i += 256) s += g_losspart[i];
    __shared__ float rs[256];
    rs[threadIdx.x] = s;
    __syncthreads();
    for (int off = 128; off; off >>= 1){
        if (threadIdx.x < off) rs[threadIdx.x] += rs[threadIdx.x+off];
        __syncthreads();
    }
    if (threadIdx.x == 0) *dst = rs[0] * (1.25f / (float)(BB*FLAT_Z));
}

// ---------------- conv_out ----------------
__global__ void __launch_bounds__(256) conv_out_k(const float* __restrict__ W,
                                                  const float* __restrict__ bias,
                                                  float* __restrict__ out)
{
    int bidx = blockIdx.x;
    int b  = bidx >> 4;
    int ot = (bidx >> 2) & 3;
    int pt = bidx & 3;
    int obase = ot * 64, pbase = pt * 64;

    __shared__ float Ws[2][16][68];
    __shared__ float Xs[2][16][68];

    int tid = threadIdx.x;
    int tx = tid & 15, ty = tid >> 4;
    int m0 = ty * 4, j0 = tx * 4;
    int lr = tid >> 2, kq = (tid & 3) * 4;
    int cl = tid >> 4, pl = (tid & 15) * 4;

    const float* Wp = W + (obase+lr)*CH + kq;

    u64 acc[4][2];
    #pragma unroll
    for (int i=0;i<4;i++){ acc[i][0]=pack2(0.f,0.f); acc[i][1]=acc[i][0]; }

    const int nt = CH/16;

    float4 wv = *(const float4*)(Wp);
    const float* src0 = g_hout + b*FLAT_PH + cl*SP + pbase + pl;
    float4 xv = *(const float4*)(src0);
    Ws[0][kq+0][lr]=wv.x; Ws[0][kq+1][lr]=wv.y; Ws[0][kq+2][lr]=wv.z; Ws[0][kq+3][lr]=wv.w;
    Xs[0][cl][pl+0]=silu_f(xv.x); Xs[0][cl][pl+1]=silu_f(xv.y);
    Xs[0][cl][pl+2]=silu_f(xv.z); Xs[0][cl][pl+3]=silu_f(xv.w);
    __syncthreads();

    for (int t = 0; t < nt; t++){
        int cur = t & 1;
        bool more = (t+1) < nt;
        if (more){
            int ck = (t+1)*16;
            wv = *(const float4*)(Wp + ck);
            const float* src = (ck < NPH) ? (g_hout + b*FLAT_PH + ck*SP)
                                          : (g_himg + b*FLAT_PH + (ck-NPH)*SP);
            xv = *(const float4*)(src + cl*SP + pbase + pl);
        }
        #pragma unroll
        for (int k=0;k<16;k++){
            float4 a = *(const float4*)&Ws[cur][k][m0];
            float4 bv = *(const float4*)&Xs[cur][k][j0];
            fma_4x4(acc, a, bv);
        }
        if (more){
            int nx = cur^1;
            Ws[nx][kq+0][lr]=wv.x; Ws[nx][kq+1][lr]=wv.y; Ws[nx][kq+2][lr]=wv.z; Ws[nx][kq+3][lr]=wv.w;
            Xs[nx][cl][pl+0]=silu_f(xv.x); Xs[nx][cl][pl+1]=silu_f(xv.y);
            Xs[nx][cl][pl+2]=silu_f(xv.z); Xs[nx][cl][pl+3]=silu_f(xv.w);
        }
        __syncthreads();
    }

    #pragma unroll
    for (int i=0;i<4;i++){
        int o = obase + m0 + i;
        float bo = bias[o];
        float v0,v1,v2,v3;
        unpack2(acc[i][0], v0, v1); unpack2(acc[i][1], v2, v3);
        float4 ov; ov.x=v0+bo; ov.y=v1+bo; ov.z=v2+bo; ov.w=v3+bo;
        *(float4*)(out + (size_t)b*(C_OUT*SP) + o*SP + pbase + j0) = ov;
    }
}

// ---------------- launcher ----------------
extern "C" void kernel_launch(void* const* d_in, const int* in_sizes, int n_in,
                              void* d_out, int out_size)
{
    (void)in_sizes; (void)n_in;
    const float* x   = (const float*)d_in[0];
    const float* ciw = (const float*)d_in[1];
    const float* cib = (const float*)d_in[2];
    const float* lnw = (const float*)d_in[3];
    const float* lnb = (const float*)d_in[4];
    const float* miw = (const float*)d_in[5];
    const float* mib = (const float*)d_in[6];
    const float* cbk = (const float*)d_in[7];
    const float* mow = (const float*)d_in[8];
    const float* mob = (const float*)d_in[9];
    const float* cow = (const float*)d_in[10];
    const float* cob = (const float*)d_in[11];
    float* out = (float*)d_out;

    float *zp_p, *z_p, *hout_p;
    u32 *aph_p, *apl_p, *zph_p, *zpl_p;
    cudaGetSymbolAddress((void**)&zp_p,   g_zp);
    cudaGetSymbolAddress((void**)&z_p,    g_z);
    cudaGetSymbolAddress((void**)&hout_p, g_hout);
    cudaGetSymbolAddress((void**)&aph_p,  g_aph);
    cudaGetSymbolAddress((void**)&apl_p,  g_apl);
    cudaGetSymbolAddress((void**)&zph_p,  g_zph);
    cudaGetSymbolAddress((void**)&zpl_p,  g_zpl);

    cudaFuncSetAttribute(mlp_mma_k, cudaFuncAttributeMaxDynamicSharedMemorySize, MMA_SMEM);

    conv_in_k<<<512, 256>>>(x, ciw, cib);
    ln_stats_k<<<64, 256>>>();
    ln_norm_k<<<dim3(64, 16), 256>>>(lnw, lnb);

    // mlp_in: 32 j-tiles x split-K 8 -> 256 CTAs, kchunk 2048
    mlp_mma_k<<<dim3(FLAT_Z/128, 8), 256, MMA_SMEM>>>(aph_p, apl_p, miw, zp_p,
                                                      FLAT_PH, FLAT_Z, FLAT_PH/8);
    combine_k<<<BB*FLAT_Z/4/256, 256>>>(zp_p, z_p, mib, 8, BB*FLAT_Z, FLAT_Z);

    cnorm_k<<<NE/256, 256>>>(cbk);
    vq_init_k<<<NROWS/256, 256>>>();
    vq_gemm_k<<<dim3(NROWS/64, NE/128), 256>>>(cbk);
    vq_gather_k<<<NROWS, 128>>>(cbk);
    z_pack_k<<<BB, 256>>>();

    // mlp_out: 128 j-tiles x split-K 2 -> 256 CTAs, kchunk 2048
    mlp_mma_k<<<dim3(FLAT_PH/128, 2), 256, MMA_SMEM>>>(zph_p, zpl_p, mow, zp_p,
                                                       FLAT_Z, FLAT_PH, FLAT_Z/2);
    combine_k<<<BB*FLAT_PH/4/256, 256>>>(zp_p, hout_p, mob, 2, BB*FLAT_PH, FLAT_PH);

    conv_out_k<<<1024, 256>>>(cow, cob, out);

    if (out_size > OUT_ELEMS)
        loss_reduce_k<<<1, 256>>>(out + out_size - 1);
}

// round 10
// speedup vs baseline: 3.5331x; 1.1198x over previous
#include <cuda_runtime.h>
#include <cuda_bf16.h>
#include <cstdint>

// ---------------- constants ----------------
#define BB 64
#define C_IN 256
#define CH 128
#define NPH 64
#define SP 256          // R*R spatial
#define ED 128
#define NE 1024
#define C_OUT 256
#define FLAT_PH 16384   // NPH*R*R
#define FLAT_Z 4096     // ED*CB*NL
#define NROWS 2048      // B*CB*NL
#define OUT_ELEMS (BB*C_OUT*SP)   // 4194304

typedef unsigned long long u64;
typedef unsigned int u32;

#define DINLINE __device__ __forceinline__

DINLINE u64 pack2(float lo, float hi){ u64 r; asm("mov.b64 %0, {%1,%2};" : "=l"(r) : "f"(lo), "f"(hi)); return r; }
DINLINE void unpack2(u64 v, float &lo, float &hi){ asm("mov.b64 {%0,%1}, %2;" : "=f"(lo), "=f"(hi) : "l"(v)); }
DINLINE u64 fma2(u64 a, u64 b, u64 c){ u64 d; asm("fma.rn.f32x2 %0, %1, %2, %3;" : "=l"(d) : "l"(a), "l"(b), "l"(c)); return d; }
DINLINE float silu_f(float x){ return x / (1.f + __expf(-x)); }

// ---- bf16 split of a pair of floats: h = bf16x2(hi parts), l = bf16x2(residuals) ----
DINLINE void split2(float x, float y, u32 &h, u32 &l){
    __nv_bfloat16 hx = __float2bfloat16(x), hy = __float2bfloat16(y);
    float rx = x - __bfloat162float(hx);
    float ry = y - __bfloat162float(hy);
    __nv_bfloat16 lx = __float2bfloat16(rx), ly = __float2bfloat16(ry);
    h = (u32)__bfloat16_as_ushort(hx) | ((u32)__bfloat16_as_ushort(hy) << 16);
    l = (u32)__bfloat16_as_ushort(lx) | ((u32)__bfloat16_as_ushort(ly) << 16);
}

DINLINE uint32_t smem_u32(const void* p){
    uint32_t a;
    asm("{ .reg .u64 t; cvta.to.shared.u64 t, %1; cvt.u32.u64 %0, t; }" : "=r"(a) : "l"(p));
    return a;
}
DINLINE void sts64(uint32_t addr, u32 a, u32 b){
    asm volatile("st.shared.v2.b32 [%0], {%1,%2};" :: "r"(addr), "r"(a), "r"(b) : "memory");
}
DINLINE void sts32(uint32_t addr, u32 a){
    asm volatile("st.shared.b32 [%0], %1;" :: "r"(addr), "r"(a) : "memory");
}
DINLINE void sts128q(uint32_t addr, u32 a, u32 b, u32 c, u32 d){
    asm volatile("st.shared.v4.b32 [%0], {%1,%2,%3,%4};" :: "r"(addr), "r"(a), "r"(b), "r"(c), "r"(d) : "memory");
}
DINLINE u32 lds32(uint32_t addr){
    u32 v; asm volatile("ld.shared.b32 %0, [%1];" : "=r"(v) : "r"(addr)); return v;
}
DINLINE void ldsm4(u32 (&r)[4], uint32_t addr){
    asm volatile("ldmatrix.sync.aligned.m8n8.x4.shared.b16 {%0,%1,%2,%3}, [%4];"
                 : "=r"(r[0]), "=r"(r[1]), "=r"(r[2]), "=r"(r[3]) : "r"(addr));
}
DINLINE void mma_bf16(float (&d)[4], const u32 (&a)[4], const u32 (&b)[2]){
    asm volatile("mma.sync.aligned.m16n8k16.row.col.f32.bf16.bf16.f32 "
                 "{%0,%1,%2,%3}, {%4,%5,%6,%7}, {%8,%9}, {%0,%1,%2,%3};"
                 : "+f"(d[0]), "+f"(d[1]), "+f"(d[2]), "+f"(d[3])
                 : "r"(a[0]), "r"(a[1]), "r"(a[2]), "r"(a[3]), "r"(b[0]), "r"(b[1]));
}

// ---------------- scratch (device globals; no allocs) ----------------
__device__ float g_hphylo[BB*FLAT_PH];   // conv_in phylo half (pre-LN)
__device__ float g_himg  [BB*FLAT_PH];   // conv_in img half (raw)
__device__ float g_stats [BB*2];         // mu, rstd per batch
__device__ float g_zp    [8*BB*FLAT_Z];  // split-K partials (8MB, shared by both MLPs)
__device__ float g_z     [BB*FLAT_Z];    // z
__device__ float g_zq    [BB*FLAT_Z];    // quantized z (fp32)
__device__ float g_hout  [BB*FLAT_PH];   // mlp_out output
__device__ float g_cnorm [NE];           // |codebook_e|^2
__device__ u64   g_key   [NROWS];        // packed (sortable_dist<<32)|idx
__device__ float g_losspart[NROWS];
// packed activations for mma GEMMs: word w at [k2][batch], bf16x2
__device__ u32   g_aph[(FLAT_PH/2)*BB];  // hn hi
__device__ u32   g_apl[(FLAT_PH/2)*BB];  // hn lo
__device__ u32   g_zph[(FLAT_Z/2)*BB];   // zq hi
__device__ u32   g_zpl[(FLAT_Z/2)*BB];   // zq lo

// ---------------- layernorm stats ----------------
__global__ void __launch_bounds__(256) ln_stats_k()
{
    int b = blockIdx.x;
    const float4* p = (const float4*)(g_hphylo + b*FLAT_PH);
    float s = 0.f, s2 = 0.f;
    for (int i = threadIdx.x; i < FLAT_PH/4; i += 256){
        float4 v = p[i];
        s  += v.x + v.y + v.z + v.w;
        s2 += v.x*v.x + v.y*v.y + v.z*v.z + v.w*v.w;
    }
    __shared__ float rs[256], rq[256];
    rs[threadIdx.x] = s; rq[threadIdx.x] = s2;
    __syncthreads();
    for (int off = 128; off; off >>= 1){
        if (threadIdx.x < off){ rs[threadIdx.x]+=rs[threadIdx.x+off]; rq[threadIdx.x]+=rq[threadIdx.x+off]; }
        __syncthreads();
    }
    if (threadIdx.x == 0){
        float mu = rs[0] * (1.f/FLAT_PH);
        float var = rq[0] * (1.f/FLAT_PH) - mu*mu;
        g_stats[b*2+0] = mu;
        g_stats[b*2+1] = rsqrtf(var + 1e-5f);
    }
}

// layernorm apply + bf16 hi/lo pack -> g_aph/g_apl ([k2][batch] layout)
__global__ void __launch_bounds__(256) ln_norm_k(const float* __restrict__ lnw,
                                                 const float* __restrict__ lnb)
{
    int b = blockIdx.x;
    int base = blockIdx.y * 1024 + threadIdx.x * 4;
    float mu = g_stats[b*2+0], rstd = g_stats[b*2+1];
    float4 v = *(const float4*)(g_hphylo + b*FLAT_PH + base);
    float4 w = *(const float4*)(lnw + base);
    float4 bb = *(const float4*)(lnb + base);
    float o0 = (v.x-mu)*rstd*w.x + bb.x;
    float o1 = (v.y-mu)*rstd*w.y + bb.y;
    float o2 = (v.z-mu)*rstd*w.z + bb.z;
    float o3 = (v.w-mu)*rstd*w.w + bb.w;
    u32 h0,l0,h1,l1;
    split2(o0,o1,h0,l0);
    split2(o2,o3,h1,l1);
    int k2 = base >> 1;
    g_aph[(size_t)k2*BB + b]     = h0;
    g_aph[(size_t)(k2+1)*BB + b] = h1;
    g_apl[(size_t)k2*BB + b]     = l0;
    g_apl[(size_t)(k2+1)*BB + b] = l1;
}

// ---------------- mma.sync bf16x3 MLP GEMM (unchanged, proven) ----------------
#define MMA_BUF 29696
#define MMA_SMEM (2*MMA_BUF)

__global__ void __launch_bounds__(256, 2)
mlp_mma_k(const u32* __restrict__ Aph, const u32* __restrict__ Apl,
          const float* __restrict__ W, float* __restrict__ C,
          int K, int N, int kchunk)
{
    extern __shared__ char dsm[];
    uint32_t sb = smem_u32(dsm);

    int tid = threadIdx.x;
    int lane = tid & 31, wid = tid >> 5;
    int g = lane >> 2, tig = lane & 3;
    int jw = (wid & 3) * 32, bw = (wid >> 2) * 32;
    int jbase = blockIdx.x * 128;
    int k0 = blockIdx.y * kchunk;
    float* Cout = C + (size_t)blockIdx.y * 64 * N;

    float dacc[2][4][4];
    #pragma unroll
    for (int m=0;m<2;m++)
        #pragma unroll
        for (int n=0;n<4;n++)
            #pragma unroll
            for (int q=0;q<4;q++) dacc[m][n][q] = 0.f;

    const int nch = kchunk >> 5;

    float4 wreg[4]; u32 ahreg[4], alreg[4];

    #pragma unroll
    for (int i=0;i<4;i++){ int idx=tid+256*i; int r=idx>>3, s=idx&7;
        wreg[i] = *(const float4*)(W + (size_t)(jbase+r)*K + k0 + s*4); }
    {
        int kb = (k0>>1);
        #pragma unroll
        for (int i=0;i<4;i++){ int idx=tid+256*i; int k2=idx>>6, b=idx&63;
            ahreg[i] = Aph[(size_t)(kb+k2)*BB + b];
            alreg[i] = Apl[(size_t)(kb+k2)*BB + b]; }
    }
    {
        uint32_t Bb = sb;
        #pragma unroll
        for (int i=0;i<4;i++){ int idx=tid+256*i; int r=idx>>3, s=idx&7;
            u32 h0,l0,h1,l1;
            split2(wreg[i].x, wreg[i].y, h0, l0);
            split2(wreg[i].z, wreg[i].w, h1, l1);
            uint32_t off = r*80 + s*8;
            sts64(Bb + off, h0, h1);
            sts64(Bb + 10240 + off, l0, l1);
        }
        #pragma unroll
        for (int i=0;i<4;i++){ int idx=tid+256*i; int k2=idx>>6, b=idx&63;
            uint32_t off = (u32)(k2*72 + b)*4;
            sts32(Bb + 20480 + off, ahreg[i]);
            sts32(Bb + 25088 + off, alreg[i]);
        }
    }
    __syncthreads();

    for (int ch = 0; ch < nch; ch++){
        int cur = ch & 1;
        bool more = (ch+1) < nch;
        if (more){
            int kk = k0 + (ch+1)*32;
            #pragma unroll
            for (int i=0;i<4;i++){ int idx=tid+256*i; int r=idx>>3, s=idx&7;
                wreg[i] = *(const float4*)(W + (size_t)(jbase+r)*K + kk + s*4); }
            int kb = (kk>>1);
            #pragma unroll
            for (int i=0;i<4;i++){ int idx=tid+256*i; int k2=idx>>6, b=idx&63;
                ahreg[i] = Aph[(size_t)(kb+k2)*BB + b];
                alreg[i] = Apl[(size_t)(kb+k2)*BB + b]; }
        }

        {
            uint32_t Bb = sb + cur*MMA_BUF;
            int lrow = ((lane>>3)&1)*8 + (lane&7);
            int lkc  = (lane>>4)*8;
            #pragma unroll
            for (int ks = 0; ks < 2; ks++){
                u32 wh[2][4], wl[2][4];
                #pragma unroll
                for (int m=0;m<2;m++){
                    uint32_t ad = Bb + (u32)((jw + m*16 + lrow)*40 + lkc + ks*16)*2;
                    ldsm4(wh[m], ad);
                    ldsm4(wl[m], ad + 10240);
                }
                u32 bh[4][2], bl[4][2];
                #pragma unroll
                for (int nf=0;nf<4;nf++){
                    uint32_t a0 = Bb + 20480 + (u32)((ks*8+tig)*72 + bw + nf*8 + g)*4;
                    bh[nf][0] = lds32(a0);
                    bh[nf][1] = lds32(a0 + 4*72*4);
                    bl[nf][0] = lds32(a0 + 4608);
                    bl[nf][1] = lds32(a0 + 4608 + 4*72*4);
                }
                #pragma unroll
                for (int m=0;m<2;m++)
                    #pragma unroll
                    for (int nf=0;nf<4;nf++){
                        mma_bf16(dacc[m][nf], wh[m], bh[nf]);
                        mma_bf16(dacc[m][nf], wh[m], bl[nf]);
                        mma_bf16(dacc[m][nf], wl[m], bh[nf]);
                    }
            }
        }

        if (more){
            uint32_t Bb = sb + (cur^1)*MMA_BUF;
            #pragma unroll
            for (int i=0;i<4;i++){ int idx=tid+256*i; int r=idx>>3, s=idx&7;
                u32 h0,l0,h1,l1;
                split2(wreg[i].x, wreg[i].y, h0, l0);
                split2(wreg[i].z, wreg[i].w, h1, l1);
                uint32_t off = r*80 + s*8;
                sts64(Bb + off, h0, h1);
                sts64(Bb + 10240 + off, l0, l1);
            }
            #pragma unroll
            for (int i=0;i<4;i++){ int idx=tid+256*i; int k2=idx>>6, b=idx&63;
                uint32_t off = (u32)(k2*72 + b)*4;
                sts32(Bb + 20480 + off, ahreg[i]);
                sts32(Bb + 25088 + off, alreg[i]);
            }
        }
        __syncthreads();
    }

    #pragma unroll
    for (int m=0;m<2;m++){
        int j = jbase + jw + m*16 + g;
        #pragma unroll
        for (int nf=0;nf<4;nf++){
            int b = bw + nf*8 + 2*tig;
            Cout[(size_t)b*N + j]         = dacc[m][nf][0];
            Cout[(size_t)(b+1)*N + j]     = dacc[m][nf][1];
            Cout[(size_t)b*N + j + 8]     = dacc[m][nf][2];
            Cout[(size_t)(b+1)*N + j + 8] = dacc[m][nf][3];
        }
    }
}

// ---------------- mma.sync bf16x3 CONV GEMM ----------------
// D[j, n] = sum_c W[j,c] * silu(X[c, n]) + bias[j], n = b*256 + p.
// X channel row c from src0 (c < csplit) else src1 (channel c-csplit); row stride 256, batch strides sb0/sb1.
// EPI 1: conv_in -> write g_hphylo (j<64) / g_himg (j>=64) fp32.
// EPI 2: conv_out -> write out[b][j][p].
// grid.x = n-tile (64 cols), grid.y = j-tile (128 rows).
template<int EPI>
__global__ void __launch_bounds__(256, 2)
conv_mma_k(const float* __restrict__ src0, const float* __restrict__ src1,
           int csplit, int sb0, int sb1,
           const float* __restrict__ W, const float* __restrict__ bias,
           float* __restrict__ out, int K)
{
    extern __shared__ char dsm[];
    uint32_t sb = smem_u32(dsm);

    int tid = threadIdx.x;
    int lane = tid & 31, wid = tid >> 5;
    int g = lane >> 2, tig = lane & 3;
    int jw = (wid & 3) * 32, bw = (wid >> 2) * 32;
    int jbase = blockIdx.y * 128;
    int nbase = blockIdx.x * 64;
    int b = nbase >> 8, pbase = nbase & 255;

    float dacc[2][4][4];
    #pragma unroll
    for (int m=0;m<2;m++)
        #pragma unroll
        for (int n=0;n<4;n++)
            #pragma unroll
            for (int q=0;q<4;q++) dacc[m][n][q] = 0.f;

    const int nch = K >> 5;
    int c2t = tid >> 4, p4 = tid & 15;   // B-load mapping: channel pair row, p quad

    float4 wreg[4], bf0, bf1;

    // prologue: load chunk 0
    #pragma unroll
    for (int i=0;i<4;i++){ int idx=tid+256*i; int r=idx>>3, s=idx&7;
        wreg[i] = *(const float4*)(W + (size_t)(jbase+r)*K + s*4); }
    {
        int c = 2*c2t;
        const float* s0 = (c < csplit) ? (src0 + (size_t)b*sb0 + c*256)
                                       : (src1 + (size_t)b*sb1 + (c-csplit)*256);
        bf0 = *(const float4*)(s0 + pbase + p4*4);
        bf1 = *(const float4*)(s0 + 256 + pbase + p4*4);
    }
    // store chunk 0 into buffer 0
    {
        uint32_t Bb = sb;
        #pragma unroll
        for (int i=0;i<4;i++){ int idx=tid+256*i; int r=idx>>3, s=idx&7;
            u32 h0,l0,h1,l1;
            split2(wreg[i].x, wreg[i].y, h0, l0);
            split2(wreg[i].z, wreg[i].w, h1, l1);
            uint32_t off = r*80 + s*8;
            sts64(Bb + off, h0, h1);
            sts64(Bb + 10240 + off, l0, l1);
        }
        u32 h[4], l[4];
        split2(silu_f(bf0.x), silu_f(bf1.x), h[0], l[0]);
        split2(silu_f(bf0.y), silu_f(bf1.y), h[1], l[1]);
        split2(silu_f(bf0.z), silu_f(bf1.z), h[2], l[2]);
        split2(silu_f(bf0.w), silu_f(bf1.w), h[3], l[3]);
        uint32_t off = (u32)(c2t*72 + p4*4)*4;
        sts128q(Bb + 20480 + off, h[0], h[1], h[2], h[3]);
        sts128q(Bb + 25088 + off, l[0], l[1], l[2], l[3]);
    }
    __syncthreads();

    for (int ch = 0; ch < nch; ch++){
        int cur = ch & 1;
        bool more = (ch+1) < nch;
        if (more){
            int kk = (ch+1)*32;
            #pragma unroll
            for (int i=0;i<4;i++){ int idx=tid+256*i; int r=idx>>3, s=idx&7;
                wreg[i] = *(const float4*)(W + (size_t)(jbase+r)*K + kk + s*4); }
            int c = kk + 2*c2t;
            const float* s0 = (c < csplit) ? (src0 + (size_t)b*sb0 + c*256)
                                           : (src1 + (size_t)b*sb1 + (c-csplit)*256);
            bf0 = *(const float4*)(s0 + pbase + p4*4);
            bf1 = *(const float4*)(s0 + 256 + pbase + p4*4);
        }

        {
            uint32_t Bb = sb + cur*MMA_BUF;
            int lrow = ((lane>>3)&1)*8 + (lane&7);
            int lkc  = (lane>>4)*8;
            #pragma unroll
            for (int ks = 0; ks < 2; ks++){
                u32 wh[2][4], wl[2][4];
                #pragma unroll
                for (int m=0;m<2;m++){
                    uint32_t ad = Bb + (u32)((jw + m*16 + lrow)*40 + lkc + ks*16)*2;
                    ldsm4(wh[m], ad);
                    ldsm4(wl[m], ad + 10240);
                }
                u32 bh[4][2], bl[4][2];
                #pragma unroll
                for (int nf=0;nf<4;nf++){
                    uint32_t a0 = Bb + 20480 + (u32)((ks*8+tig)*72 + bw + nf*8 + g)*4;
                    bh[nf][0] = lds32(a0);
                    bh[nf][1] = lds32(a0 + 4*72*4);
                    bl[nf][0] = lds32(a0 + 4608);
                    bl[nf][1] = lds32(a0 + 4608 + 4*72*4);
                }
                #pragma unroll
                for (int m=0;m<2;m++)
                    #pragma unroll
                    for (int nf=0;nf<4;nf++){
                        mma_bf16(dacc[m][nf], wh[m], bh[nf]);
                        mma_bf16(dacc[m][nf], wh[m], bl[nf]);
                        mma_bf16(dacc[m][nf], wl[m], bh[nf]);
                    }
            }
        }

        if (more){
            uint32_t Bb = sb + (cur^1)*MMA_BUF;
            #pragma unroll
            for (int i=0;i<4;i++){ int idx=tid+256*i; int r=idx>>3, s=idx&7;
                u32 h0,l0,h1,l1;
                split2(wreg[i].x, wreg[i].y, h0, l0);
                split2(wreg[i].z, wreg[i].w, h1, l1);
                uint32_t off = r*80 + s*8;
                sts64(Bb + off, h0, h1);
                sts64(Bb + 10240 + off, l0, l1);
            }
            u32 h[4], l[4];
            split2(silu_f(bf0.x), silu_f(bf1.x), h[0], l[0]);
            split2(silu_f(bf0.y), silu_f(bf1.y), h[1], l[1]);
            split2(silu_f(bf0.z), silu_f(bf1.z), h[2], l[2]);
            split2(silu_f(bf0.w), silu_f(bf1.w), h[3], l[3]);
            uint32_t off = (u32)(c2t*72 + p4*4)*4;
            sts128q(Bb + 20480 + off, h[0], h[1], h[2], h[3]);
            sts128q(Bb + 25088 + off, l[0], l[1], l[2], l[3]);
        }
        __syncthreads();
    }

    // epilogue
    #pragma unroll
    for (int m=0;m<2;m++){
        int j = jbase + jw + m*16 + g;
        float b0v = bias[j], b1v = bias[j+8];
        #pragma unroll
        for (int nf=0;nf<4;nf++){
            int p = pbase + bw + nf*8 + 2*tig;
            float v0 = dacc[m][nf][0] + b0v, v1 = dacc[m][nf][1] + b0v;
            float v2 = dacc[m][nf][2] + b1v, v3 = dacc[m][nf][3] + b1v;
            if (EPI == 1){
                float* d0 = (j < NPH) ? (g_hphylo + (size_t)b*FLAT_PH + j*256 + p)
                                      : (g_himg   + (size_t)b*FLAT_PH + (j-NPH)*256 + p);
                *(float2*)d0          = make_float2(v0, v1);
                *(float2*)(d0 + 2048) = make_float2(v2, v3);
            } else {
                float* d0 = out + (size_t)b*(C_OUT*SP) + (size_t)j*256 + p;
                *(float2*)d0          = make_float2(v0, v1);
                *(float2*)(d0 + 2048) = make_float2(v2, v3);
            }
        }
    }
}

// ---------------- combine nsplit partials + bias ----------------
__global__ void __launch_bounds__(256) combine_k(const float* __restrict__ P,
                                                 float* __restrict__ out,
                                                 const float* __restrict__ bias,
                                                 int nsplit, int total, int N)
{
    int i = blockIdx.x * 256 + threadIdx.x;
    const float4* P4 = (const float4*)P;
    float4 s = P4[i];
    int stride = total >> 2;
    for (int sp = 1; sp < nsplit; sp++){
        float4 a = P4[i + sp*stride];
        s.x+=a.x; s.y+=a.y; s.z+=a.z; s.w+=a.w;
    }
    int j = (i * 4) & (N - 1);
    float4 bv = *(const float4*)(bias + j);
    s.x+=bv.x; s.y+=bv.y; s.z+=bv.z; s.w+=bv.w;
    ((float4*)out)[i] = s;
}

// ---------------- codebook norms ----------------
__global__ void __launch_bounds__(256) cnorm_k(const float* __restrict__ cb)
{
    int e = blockIdx.x * 256 + threadIdx.x;
    const float4* r = (const float4*)(cb + e*ED);
    float s = 0.f;
    #pragma unroll 8
    for (int i = 0; i < ED/4; i++){
        float4 v = r[i];
        s += v.x*v.x + v.y*v.y + v.z*v.z + v.w*v.w;
    }
    g_cnorm[e] = s;
}

__global__ void __launch_bounds__(256) vq_init_k()
{
    int i = blockIdx.x * 256 + threadIdx.x;
    g_key[i] = ~0ULL;
    g_losspart[i] = 0.f;
}

// ---------------- VQ distance GEMM + argmin ----------------
__global__ void __launch_bounds__(256) vq_gemm_k(const float* __restrict__ cb)
{
    int rbase = blockIdx.x * 64;
    int ebase = blockIdx.y * 128;
    int b0 = rbase >> 5;

    __shared__ float Zs[32][68];
    __shared__ float Cs[32][132];
    __shared__ float cn[128];

    int tid = threadIdx.x;
    if (tid < 128) cn[tid] = g_cnorm[ebase + tid];
    int tx = tid & 15, ty = tid >> 4;
    int r0 = ty * 4, e0 = tx * 8;

    u64 acc2[4][4];
    #pragma unroll
    for (int i=0;i<4;i++)
        #pragma unroll
        for (int j=0;j<4;j++) acc2[i][j] = pack2(0.f,0.f);

    for (int kc = 0; kc < ED; kc += 32){
        #pragma unroll
        for (int it = 0; it < 2; it++){
            int i = tid + it*256;
            int brel = i >> 8;
            int t = (i & 255) * 4;
            float4 v = *(const float4*)(g_z + (b0+brel)*FLAT_Z + kc*32 + t);
            int k = t >> 5, s = t & 31;
            *(float4*)&Zs[k][brel*32 + s] = v;
        }
        #pragma unroll
        for (int it = 0; it < 4; it++){
            int i = tid + it*256;
            int el = i >> 3; int kq = (i & 7) * 4;
            float4 v = *(const float4*)(cb + (ebase+el)*ED + kc + kq);
            Cs[kq+0][el]=v.x; Cs[kq+1][el]=v.y; Cs[kq+2][el]=v.z; Cs[kq+3][el]=v.w;
        }
        __syncthreads();
        #pragma unroll 4
        for (int k = 0; k < 32; k++){
            float4 a  = *(const float4*)&Zs[k][r0];
            float4 c0 = *(const float4*)&Cs[k][e0];
            float4 c1 = *(const float4*)&Cs[k][e0+4];
            u64 cp[4] = {pack2(c0.x,c0.y), pack2(c0.z,c0.w),
                         pack2(c1.x,c1.y), pack2(c1.z,c1.w)};
            float av[4] = {a.x,a.y,a.z,a.w};
            #pragma unroll
            for (int i=0;i<4;i++){
                u64 aa = pack2(av[i], av[i]);
                #pragma unroll
                for (int j=0;j<4;j++) acc2[i][j] = fma2(aa, cp[j], acc2[i][j]);
            }
        }
        __syncthreads();
    }

    #pragma unroll
    for (int i=0;i<4;i++){
        float best = 3.4e38f; int be = 0;
        #pragma unroll
        for (int j=0;j<4;j++){
            float d0, d1;
            unpack2(acc2[i][j], d0, d1);
            float da = cn[e0+2*j]   - 2.f*d0;
            float db = cn[e0+2*j+1] - 2.f*d1;
            if (da < best){ best = da; be = e0+2*j; }
            if (db < best){ best = db; be = e0+2*j+1; }
        }
        unsigned int bits = __float_as_uint(best);
        unsigned int key32 = (bits & 0x80000000u) ? ~bits : (bits | 0x80000000u);
        u64 key = ((u64)key32 << 32) | (unsigned)(ebase + be);
        atomicMin(&g_key[rbase + r0 + i], key);
    }
}

// ---------------- gather zq (fp32) + per-row loss partial ----------------
__global__ void __launch_bounds__(128) vq_gather_k(const float* __restrict__ cb)
{
    int r = blockIdx.x;
    int b = r >> 5, s = r & 31;
    int e = (int)(unsigned)(g_key[r] & 0xFFFFFFFFULL);
    int k = threadIdx.x;
    float c = cb[e*ED + k];
    float z = g_z[b*FLAT_Z + k*32 + s];
    g_zq[b*FLAT_Z + k*32 + s] = c;
    float d = c - z; d = d * d;
    #pragma unroll
    for (int off = 16; off; off >>= 1) d += __shfl_down_sync(0xffffffffu, d, off);
    __shared__ float red[4];
    if ((threadIdx.x & 31) == 0) red[threadIdx.x >> 5] = d;
    __syncthreads();
    if (threadIdx.x == 0) g_losspart[r] = red[0]+red[1]+red[2]+red[3];
}

// pack zq into bf16 hi/lo [k2][batch] words
__global__ void __launch_bounds__(256) z_pack_k()
{
    int b = blockIdx.x;
    for (int w = threadIdx.x; w < FLAT_Z/2; w += 256){
        float f0 = g_zq[b*FLAT_Z + 2*w];
        float f1 = g_zq[b*FLAT_Z + 2*w + 1];
        u32 h, l;
        split2(f0, f1, h, l);
        g_zph[(size_t)w*BB + b] = h;
        g_zpl[(size_t)w*BB + b] = l;
    }
}

__global__ void __launch_bounds__(256) loss_reduce_k(float* __restrict__ dst)
{
    float s = 0.f;
    for (int i = threadIdx.x; i < NROWS; i += 256) s += g_losspart[i];
    __shared__ float rs[256];
    rs[threadIdx.x] = s;
    __syncthreads();
    for (int off = 128; off; off >>= 1){
        if (threadIdx.x < off) rs[threadIdx.x] += rs[threadIdx.x+off];
        __syncthreads();
    }
    if (threadIdx.x == 0) *dst = rs[0] * (1.25f / (float)(BB*FLAT_Z));
}

// ---------------- launcher ----------------
extern "C" void kernel_launch(void* const* d_in, const int* in_sizes, int n_in,
                              void* d_out, int out_size)
{
    (void)in_sizes; (void)n_in;
    const float* x   = (const float*)d_in[0];
    const float* ciw = (const float*)d_in[1];
    const float* cib = (const float*)d_in[2];
    const float* lnw = (const float*)d_in[3];
    const float* lnb = (const float*)d_in[4];
    const float* miw = (const float*)d_in[5];
    const float* mib = (const float*)d_in[6];
    const float* cbk = (const float*)d_in[7];
    const float* mow = (const float*)d_in[8];
    const float* mob = (const float*)d_in[9];
    const float* cow = (const float*)d_in[10];
    const float* cob = (const float*)d_in[11];
    float* out = (float*)d_out;

    float *zp_p, *z_p, *hout_p, *himg_p;
    u32 *aph_p, *apl_p, *zph_p, *zpl_p;
    cudaGetSymbolAddress((void**)&zp_p,   g_zp);
    cudaGetSymbolAddress((void**)&z_p,    g_z);
    cudaGetSymbolAddress((void**)&hout_p, g_hout);
    cudaGetSymbolAddress((void**)&himg_p, g_himg);
    cudaGetSymbolAddress((void**)&aph_p,  g_aph);
    cudaGetSymbolAddress((void**)&apl_p,  g_apl);
    cudaGetSymbolAddress((void**)&zph_p,  g_zph);
    cudaGetSymbolAddress((void**)&zpl_p,  g_zpl);

    cudaFuncSetAttribute(mlp_mma_k, cudaFuncAttributeMaxDynamicSharedMemorySize, MMA_SMEM);
    cudaFuncSetAttribute(conv_mma_k<1>, cudaFuncAttributeMaxDynamicSharedMemorySize, MMA_SMEM);
    cudaFuncSetAttribute(conv_mma_k<2>, cudaFuncAttributeMaxDynamicSharedMemorySize, MMA_SMEM);

    // conv_in: 256 n-tiles x 1 j-tile; X = silu(x), K=256
    conv_mma_k<1><<<dim3(256, 1), 256, MMA_SMEM>>>(x, x, 4096, C_IN*SP, C_IN*SP,
                                                   ciw, cib, nullptr, C_IN);

    ln_stats_k<<<64, 256>>>();
    ln_norm_k<<<dim3(64, 16), 256>>>(lnw, lnb);

    // mlp_in: 32 j-tiles x split-K 8 -> 256 CTAs
    mlp_mma_k<<<dim3(FLAT_Z/128, 8), 256, MMA_SMEM>>>(aph_p, apl_p, miw, zp_p,
                                                      FLAT_PH, FLAT_Z, FLAT_PH/8);
    combine_k<<<BB*FLAT_Z/4/256, 256>>>(zp_p, z_p, mib, 8, BB*FLAT_Z, FLAT_Z);

    cnorm_k<<<NE/256, 256>>>(cbk);
    vq_init_k<<<NROWS/256, 256>>>();
    vq_gemm_k<<<dim3(NROWS/64, NE/128), 256>>>(cbk);
    vq_gather_k<<<NROWS, 128>>>(cbk);
    z_pack_k<<<BB, 256>>>();

    // mlp_out: 128 j-tiles x split-K 2 -> 256 CTAs
    mlp_mma_k<<<dim3(FLAT_PH/128, 2), 256, MMA_SMEM>>>(zph_p, zpl_p, mow, zp_p,
                                                       FLAT_Z, FLAT_PH, FLAT_Z/2);
    combine_k<<<BB*FLAT_PH/4/256, 256>>>(zp_p, hout_p, mob, 2, BB*FLAT_PH, FLAT_PH);

    // conv_out: 256 n-tiles x 2 j-tiles; X = silu(concat(hout, himg)), K=128
    conv_mma_k<2><<<dim3(256, 2), 256, MMA_SMEM>>>(hout_p, himg_p, NPH, FLAT_PH, FLAT_PH,
                                                   cow, cob, out, CH);

    if (out_size > OUT_ELEMS)
        loss_reduce_k<<<1, 256>>>(out + out_size - 1);
}